// round 2
// baseline (speedup 1.0000x reference)
#include <cuda_runtime.h>
#include <cuda_bf16.h>
#include <cstdint>

// Problem constants (from reference)
#define NN 50000
#define FIN 128
#define FOUT 40
#define EMAX 1600000
#define BN_EPS 1e-5f

// ---------------- device scratch (no allocations allowed) ----------------
__device__ float d_t0[NN * FIN];            // gemm output
__device__ float d_t1[NN * FIN];            // spmm output (layer activations)
__device__ float d_t2[NN * FOUT + 64];      // layer-2 gemm output (padded)
__device__ int2  d_ecolw[EMAX];             // CSR-sorted (col, weight-bits)
__device__ int   d_counts[NN];
__device__ int   d_rowptr[NN + 1];
__device__ int   d_cursor[NN];
__device__ float d_sum[2][FIN];
__device__ float d_sumsq[2][FIN];
__device__ float d_scale[2][FIN];
__device__ float d_shift[2][FIN];

// ---------------- CSR build ----------------
__global__ void zero_kernel() {
    int i = blockIdx.x * blockDim.x + threadIdx.x;
    if (i < NN) d_counts[i] = 0;
    if (i < FIN) {
        d_sum[0][i] = 0.f; d_sum[1][i] = 0.f;
        d_sumsq[0][i] = 0.f; d_sumsq[1][i] = 0.f;
    }
}

__global__ void hist_kernel(const int* __restrict__ er, int E) {
    int e = blockIdx.x * blockDim.x + threadIdx.x;
    if (e < E) atomicAdd(&d_counts[er[e]], 1);
}

__global__ void scan_kernel(int Nn) {
    __shared__ int ssum[1024];
    int t = threadIdx.x;
    int chunk = (Nn + 1023) >> 10;
    int base = t * chunk;
    int s = 0;
    for (int i = 0; i < chunk; ++i) {
        int idx = base + i;
        if (idx < Nn) s += d_counts[idx];
    }
    ssum[t] = s;
    __syncthreads();
    // Hillis-Steele inclusive scan
    for (int off = 1; off < 1024; off <<= 1) {
        int v = (t >= off) ? ssum[t - off] : 0;
        __syncthreads();
        ssum[t] += v;
        __syncthreads();
    }
    int run = (t > 0) ? ssum[t - 1] : 0;
    for (int i = 0; i < chunk; ++i) {
        int idx = base + i;
        if (idx < Nn) {
            d_rowptr[idx] = run;
            d_cursor[idx] = run;
            run += d_counts[idx];
        }
    }
    if (t == 1023) d_rowptr[Nn] = run;
}

__global__ void scatter_kernel(const int* __restrict__ er, const int* __restrict__ ec,
                               const float* __restrict__ ew, int E) {
    int e = blockIdx.x * blockDim.x + threadIdx.x;
    if (e >= E) return;
    int r = er[e];
    int pos = atomicAdd(&d_cursor[r], 1);
    d_ecolw[pos] = make_int2(ec[e], __float_as_int(ew[e]));
}

// ---------------- GEMM: out[M,F] = act(X[M,128]) @ W[128,F] ----------------
// act = identity (layer 0) or relu(bn(x)) via per-feature scale/shift.
// Block: 64 rows x F cols, 256 threads (32x8), thread tile 8 rows x TN cols.
template <int F, bool BN>
__global__ __launch_bounds__(256) void gemm_kernel(
    const float* __restrict__ X, const float* __restrict__ W,
    float* __restrict__ out, int layer, int M)
{
    constexpr int TN = (F + 31) / 32;
    __shared__ float Xs[64][64];
    __shared__ float Ws[64][F];

    const int tx = threadIdx.x;        // 0..31 (cols)
    const int ty = threadIdx.y;        // 0..7  (row groups)
    const int tid = ty * 32 + tx;
    const int row0 = blockIdx.x * 64;

    float acc[8][TN];
#pragma unroll
    for (int i = 0; i < 8; ++i)
#pragma unroll
        for (int j = 0; j < TN; ++j) acc[i][j] = 0.f;

    for (int kt = 0; kt < 2; ++kt) {
        const int k0 = kt * 64;
        // load W chunk: rows k0..k0+63, F cols
        {
            const int nv4 = 64 * F / 4;
            for (int idx = tid; idx < nv4; idx += 256) {
                int r = idx / (F / 4);
                int c4 = idx % (F / 4);
                float4 v = *reinterpret_cast<const float4*>(&W[(k0 + r) * F + c4 * 4]);
                *reinterpret_cast<float4*>(&Ws[r][c4 * 4]) = v;
            }
        }
        // load X chunk (with optional BN+ReLU): rows row0..row0+63, cols k0..k0+63
        {
#pragma unroll
            for (int l = 0; l < 4; ++l) {
                int idx = tid + 256 * l;
                int r = idx >> 4;
                int c4 = idx & 15;
                int grow = row0 + r;
                float4 v = make_float4(0.f, 0.f, 0.f, 0.f);
                if (grow < M)
                    v = *reinterpret_cast<const float4*>(&X[grow * FIN + k0 + c4 * 4]);
                if (BN) {
                    int k = k0 + c4 * 4;
                    v.x = fmaxf(v.x * d_scale[layer][k + 0] + d_shift[layer][k + 0], 0.f);
                    v.y = fmaxf(v.y * d_scale[layer][k + 1] + d_shift[layer][k + 1], 0.f);
                    v.z = fmaxf(v.z * d_scale[layer][k + 2] + d_shift[layer][k + 2], 0.f);
                    v.w = fmaxf(v.w * d_scale[layer][k + 3] + d_shift[layer][k + 3], 0.f);
                }
                *reinterpret_cast<float4*>(&Xs[r][c4 * 4]) = v;
            }
        }
        __syncthreads();

#pragma unroll 4
        for (int kk = 0; kk < 64; ++kk) {
            float b[TN];
#pragma unroll
            for (int j = 0; j < TN; ++j) {
                int c = tx + 32 * j;
                b[j] = (c < F) ? Ws[kk][c] : 0.f;
            }
#pragma unroll
            for (int i = 0; i < 8; ++i) {
                float a = Xs[ty + 8 * i][kk];
#pragma unroll
                for (int j = 0; j < TN; ++j) acc[i][j] += a * b[j];
            }
        }
        __syncthreads();
    }

#pragma unroll
    for (int i = 0; i < 8; ++i) {
        int grow = row0 + ty + 8 * i;
        if (grow < M) {
#pragma unroll
            for (int j = 0; j < TN; ++j) {
                int c = tx + 32 * j;
                if (c < F) out[grow * F + c] = acc[i][j];
            }
        }
    }
}

// ---------------- SpMM: out[row,:] = sum_e w_e * h[col_e,:] + bias ----------------
template <int F>
__global__ void spmm_kernel(const float* __restrict__ h,
                            const float* __restrict__ bias,
                            float* __restrict__ out)
{
    const int row = blockIdx.x;
    const int f = threadIdx.x;
    if (f >= F) return;
    const int s = d_rowptr[row];
    const int e = d_rowptr[row + 1];
    float acc = 0.f;
    int i = s;
    for (; i + 4 <= e; i += 4) {
        int2 e0 = d_ecolw[i + 0];
        int2 e1 = d_ecolw[i + 1];
        int2 e2 = d_ecolw[i + 2];
        int2 e3 = d_ecolw[i + 3];
        float h0 = __ldg(&h[e0.x * F + f]);
        float h1 = __ldg(&h[e1.x * F + f]);
        float h2 = __ldg(&h[e2.x * F + f]);
        float h3 = __ldg(&h[e3.x * F + f]);
        acc += __int_as_float(e0.y) * h0;
        acc += __int_as_float(e1.y) * h1;
        acc += __int_as_float(e2.y) * h2;
        acc += __int_as_float(e3.y) * h3;
    }
    for (; i < e; ++i) {
        int2 ed = d_ecolw[i];
        acc += __int_as_float(ed.y) * __ldg(&h[ed.x * F + f]);
    }
    out[row * F + f] = acc + bias[f];
}

// ---------------- BatchNorm stats & finalize ----------------
__global__ void bnstats_kernel(const float* __restrict__ t, int layer) {
    const int f = threadIdx.x;   // 0..127
    float s = 0.f, s2 = 0.f;
    for (int r = blockIdx.x; r < NN; r += gridDim.x) {
        float v = t[r * FIN + f];
        s += v;
        s2 += v * v;
    }
    atomicAdd(&d_sum[layer][f], s);
    atomicAdd(&d_sumsq[layer][f], s2);
}

__global__ void bnfin_kernel(const float* __restrict__ g, const float* __restrict__ be, int layer) {
    const int f = threadIdx.x;
    const float invN = 1.f / (float)NN;
    float mean = d_sum[layer][f] * invN;
    float var = d_sumsq[layer][f] * invN - mean * mean;
    float rstd = rsqrtf(var + BN_EPS);
    float sc = g[f] * rstd;
    d_scale[layer][f] = sc;
    d_shift[layer][f] = be[f] - mean * sc;
}

// ---------------- launch ----------------
extern "C" void kernel_launch(void* const* d_in, const int* in_sizes, int n_in,
                              void* d_out, int out_size)
{
    const float* x   = (const float*)d_in[0];
    const int*   er  = (const int*)d_in[1];
    const int*   ec  = (const int*)d_in[2];
    const float* ew  = (const float*)d_in[3];
    const float* W0  = (const float*)d_in[4];
    const float* b0  = (const float*)d_in[5];
    const float* g0  = (const float*)d_in[6];
    const float* be0 = (const float*)d_in[7];
    const float* W1  = (const float*)d_in[8];
    const float* b1  = (const float*)d_in[9];
    const float* g1  = (const float*)d_in[10];
    const float* be1 = (const float*)d_in[11];
    const float* W2  = (const float*)d_in[12];
    const float* b2  = (const float*)d_in[13];
    float* out = (float*)d_out;

    const int M = in_sizes[0] / FIN;   // 50000
    const int E = in_sizes[1];         // 1600000

    float* t0; cudaGetSymbolAddress((void**)&t0, d_t0);
    float* t1; cudaGetSymbolAddress((void**)&t1, d_t1);
    float* t2; cudaGetSymbolAddress((void**)&t2, d_t2);

    // CSR build
    zero_kernel<<<(NN + 255) / 256, 256>>>();
    hist_kernel<<<(E + 255) / 256, 256>>>(er, E);
    scan_kernel<<<1, 1024>>>(M);
    scatter_kernel<<<(E + 255) / 256, 256>>>(er, ec, ew, E);

    const int gblk = (M + 63) / 64;
    dim3 gthr(32, 8);

    // layer 0
    gemm_kernel<FIN, false><<<gblk, gthr>>>(x, W0, t0, 0, M);
    spmm_kernel<FIN><<<M, 128>>>(t0, b0, t1);
    bnstats_kernel<<<512, 128>>>(t1, 0);
    bnfin_kernel<<<1, 128>>>(g0, be0, 0);

    // layer 1 (BN+ReLU of t1 fused into gemm X-load)
    gemm_kernel<FIN, true><<<gblk, gthr>>>(t1, W1, t0, 0, M);
    spmm_kernel<FIN><<<M, 128>>>(t0, b1, t1);
    bnstats_kernel<<<512, 128>>>(t1, 1);
    bnfin_kernel<<<1, 128>>>(g1, be1, 1);

    // layer 2 (final conv, F=40)
    gemm_kernel<FOUT, true><<<gblk, gthr>>>(t1, W2, t2, 1, M);
    spmm_kernel<FOUT><<<M, 64>>>(t2, b2, out);
}

// round 4
// speedup vs baseline: 1.3395x; 1.3395x over previous
#include <cuda_runtime.h>
#include <cuda_bf16.h>
#include <cstdint>

#define NN 50000
#define FIN 128
#define FOUT 40
#define EMAX 1600000
#define BN_EPS 1e-5f

// ---------------- device scratch ----------------
__device__ float d_t0[NN * FIN];            // gemm output
__device__ float d_t1[NN * FIN];            // spmm output (activations)
__device__ float d_t2[NN * FOUT + 64];      // layer-2 gemm output
__device__ int2  d_ecolw[EMAX];             // CSR-sorted (col, weight-bits)
__device__ int   d_epos[EMAX];              // intra-row position per edge
__device__ int   d_counts[NN];
__device__ int   d_rowptr[NN + 1];
__device__ float d_sum[2][FIN];
__device__ float d_sumsq[2][FIN];
__device__ float d_scale[2][FIN];
__device__ float d_shift[2][FIN];

// ---------------- CSR build ----------------
__global__ void zero_kernel() {
    int i = blockIdx.x * blockDim.x + threadIdx.x;
    if (i < NN) d_counts[i] = 0;
    if (i < FIN) {
        d_sum[0][i] = 0.f; d_sum[1][i] = 0.f;
        d_sumsq[0][i] = 0.f; d_sumsq[1][i] = 0.f;
    }
}

__global__ void hist_kernel(const int* __restrict__ er, int E) {
    int e = blockIdx.x * blockDim.x + threadIdx.x;
    if (e < E) d_epos[e] = atomicAdd(&d_counts[er[e]], 1);
}

__global__ void scan_kernel(int Nn) {
    __shared__ int ssum[1024];
    int t = threadIdx.x;
    int chunk = (Nn + 1023) >> 10;
    int base = t * chunk;
    int s = 0;
    for (int i = 0; i < chunk; ++i) {
        int idx = base + i;
        if (idx < Nn) s += d_counts[idx];
    }
    ssum[t] = s;
    __syncthreads();
    for (int off = 1; off < 1024; off <<= 1) {
        int v = (t >= off) ? ssum[t - off] : 0;
        __syncthreads();
        ssum[t] += v;
        __syncthreads();
    }
    int run = (t > 0) ? ssum[t - 1] : 0;
    for (int i = 0; i < chunk; ++i) {
        int idx = base + i;
        if (idx < Nn) {
            d_rowptr[idx] = run;
            run += d_counts[idx];
        }
    }
    if (t == 1023) d_rowptr[Nn] = run;
}

__global__ void scatter_kernel(const int* __restrict__ er, const int* __restrict__ ec,
                               const float* __restrict__ ew, int E) {
    int e = blockIdx.x * blockDim.x + threadIdx.x;
    if (e >= E) return;
    int pos = d_rowptr[er[e]] + d_epos[e];
    d_ecolw[pos] = make_int2(ec[e], __float_as_int(ew[e]));
}

// ---------------- GEMM 128x128: out = act(X) @ W ----------------
// Block: 128 rows x 128 cols, 256 threads, 8x8 thread tile, float4 LDS.
template <bool BN>
__global__ __launch_bounds__(256) void gemm128_kernel(
    const float* __restrict__ X, const float* __restrict__ W,
    float* __restrict__ out, int layer, int M)
{
    __shared__ float Xt[32][132];   // [k][row] transposed
    __shared__ float Ws[32][132];   // [k][col]

    const int tid = threadIdx.x;
    const int tx = tid & 15;        // col group 0..15
    const int ty = tid >> 4;        // row group 0..15
    const int row0 = blockIdx.x * 128;

    float acc[8][8];
#pragma unroll
    for (int i = 0; i < 8; ++i)
#pragma unroll
        for (int j = 0; j < 8; ++j) acc[i][j] = 0.f;

    for (int kt = 0; kt < 4; ++kt) {
        const int k0 = kt * 32;
        // W chunk: rows k0..k0+31, 128 cols
#pragma unroll
        for (int l = 0; l < 4; ++l) {
            int idx = tid + 256 * l;
            int kk = idx >> 5;
            int c4 = idx & 31;
            float4 v = *reinterpret_cast<const float4*>(&W[(k0 + kk) * 128 + c4 * 4]);
            *reinterpret_cast<float4*>(&Ws[kk][c4 * 4]) = v;
        }
        // X chunk transposed (+ optional BN+ReLU)
#pragma unroll
        for (int l = 0; l < 4; ++l) {
            int idx = tid + 256 * l;
            int r = idx >> 3;       // 0..127
            int c4 = idx & 7;       // k-offset/4
            int grow = row0 + r;
            float4 v = make_float4(0.f, 0.f, 0.f, 0.f);
            if (grow < M)
                v = *reinterpret_cast<const float4*>(&X[grow * 128 + k0 + c4 * 4]);
            int k = k0 + c4 * 4;
            if (BN) {
                v.x = fmaxf(fmaf(v.x, d_scale[layer][k + 0], d_shift[layer][k + 0]), 0.f);
                v.y = fmaxf(fmaf(v.y, d_scale[layer][k + 1], d_shift[layer][k + 1]), 0.f);
                v.z = fmaxf(fmaf(v.z, d_scale[layer][k + 2], d_shift[layer][k + 2]), 0.f);
                v.w = fmaxf(fmaf(v.w, d_scale[layer][k + 3], d_shift[layer][k + 3]), 0.f);
            }
            Xt[c4 * 4 + 0][r] = v.x;
            Xt[c4 * 4 + 1][r] = v.y;
            Xt[c4 * 4 + 2][r] = v.z;
            Xt[c4 * 4 + 3][r] = v.w;
        }
        __syncthreads();

#pragma unroll 8
        for (int kk = 0; kk < 32; ++kk) {
            float4 a0 = *reinterpret_cast<const float4*>(&Xt[kk][ty * 8]);
            float4 a1 = *reinterpret_cast<const float4*>(&Xt[kk][ty * 8 + 4]);
            float4 b0 = *reinterpret_cast<const float4*>(&Ws[kk][tx * 8]);
            float4 b1 = *reinterpret_cast<const float4*>(&Ws[kk][tx * 8 + 4]);
            float a[8] = {a0.x, a0.y, a0.z, a0.w, a1.x, a1.y, a1.z, a1.w};
            float b[8] = {b0.x, b0.y, b0.z, b0.w, b1.x, b1.y, b1.z, b1.w};
#pragma unroll
            for (int i = 0; i < 8; ++i)
#pragma unroll
                for (int j = 0; j < 8; ++j)
                    acc[i][j] = fmaf(a[i], b[j], acc[i][j]);
        }
        __syncthreads();
    }

#pragma unroll
    for (int i = 0; i < 8; ++i) {
        int grow = row0 + ty * 8 + i;
        if (grow < M) {
            float4 o0 = make_float4(acc[i][0], acc[i][1], acc[i][2], acc[i][3]);
            float4 o1 = make_float4(acc[i][4], acc[i][5], acc[i][6], acc[i][7]);
            *reinterpret_cast<float4*>(&out[grow * 128 + tx * 8]) = o0;
            *reinterpret_cast<float4*>(&out[grow * 128 + tx * 8 + 4]) = o1;
        }
    }
}

// ---------------- GEMM F=40 (final layer) ----------------
__global__ __launch_bounds__(256) void gemm40_kernel(
    const float* __restrict__ X, const float* __restrict__ W,
    float* __restrict__ out, int layer, int M)
{
    constexpr int F = FOUT;
    __shared__ float Xs[64][64];
    __shared__ float Ws[64][F];

    const int tx = threadIdx.x;
    const int ty = threadIdx.y;
    const int tid = ty * 32 + tx;
    const int row0 = blockIdx.x * 64;

    float acc[8][2];
#pragma unroll
    for (int i = 0; i < 8; ++i) { acc[i][0] = 0.f; acc[i][1] = 0.f; }

    for (int kt = 0; kt < 2; ++kt) {
        const int k0 = kt * 64;
        {
            const int nv4 = 64 * F / 4;
            for (int idx = tid; idx < nv4; idx += 256) {
                int r = idx / (F / 4);
                int c4 = idx % (F / 4);
                float4 v = *reinterpret_cast<const float4*>(&W[(k0 + r) * F + c4 * 4]);
                *reinterpret_cast<float4*>(&Ws[r][c4 * 4]) = v;
            }
        }
        {
#pragma unroll
            for (int l = 0; l < 4; ++l) {
                int idx = tid + 256 * l;
                int r = idx >> 4;
                int c4 = idx & 15;
                int grow = row0 + r;
                float4 v = make_float4(0.f, 0.f, 0.f, 0.f);
                if (grow < M)
                    v = *reinterpret_cast<const float4*>(&X[grow * FIN + k0 + c4 * 4]);
                int k = k0 + c4 * 4;
                v.x = fmaxf(fmaf(v.x, d_scale[layer][k + 0], d_shift[layer][k + 0]), 0.f);
                v.y = fmaxf(fmaf(v.y, d_scale[layer][k + 1], d_shift[layer][k + 1]), 0.f);
                v.z = fmaxf(fmaf(v.z, d_scale[layer][k + 2], d_shift[layer][k + 2]), 0.f);
                v.w = fmaxf(fmaf(v.w, d_scale[layer][k + 3], d_shift[layer][k + 3]), 0.f);
                *reinterpret_cast<float4*>(&Xs[r][c4 * 4]) = v;
            }
        }
        __syncthreads();

#pragma unroll 4
        for (int kk = 0; kk < 64; ++kk) {
            float b0 = Ws[kk][tx];
            float b1 = (tx < 8) ? Ws[kk][32 + tx] : 0.f;
#pragma unroll
            for (int i = 0; i < 8; ++i) {
                float a = Xs[ty + 8 * i][kk];
                acc[i][0] = fmaf(a, b0, acc[i][0]);
                acc[i][1] = fmaf(a, b1, acc[i][1]);
            }
        }
        __syncthreads();
    }

#pragma unroll
    for (int i = 0; i < 8; ++i) {
        int grow = row0 + ty + 8 * i;
        if (grow < M) {
            out[grow * F + tx] = acc[i][0];
            if (tx < 8) out[grow * F + 32 + tx] = acc[i][1];
        }
    }
}

// ---------------- SpMM F=128: warp per row, float4 gathers ----------------
__global__ __launch_bounds__(256) void spmm128_kernel(
    const float* __restrict__ h, const float* __restrict__ bias,
    float* __restrict__ out, int M)
{
    const int warp = blockIdx.x * 8 + (threadIdx.x >> 5);
    const int lane = threadIdx.x & 31;
    if (warp >= M) return;
    const int s = d_rowptr[warp];
    const int e = d_rowptr[warp + 1];
    const float4* __restrict__ h4 = reinterpret_cast<const float4*>(h);

    float4 acc = make_float4(0.f, 0.f, 0.f, 0.f);
    int base = s;
    for (; base + 32 <= e; base += 32) {
        int2 md = d_ecolw[base + lane];
        int colr = md.x;
        float wr = __int_as_float(md.y);
#pragma unroll
        for (int j = 0; j < 32; ++j) {
            int col = __shfl_sync(0xffffffffu, colr, j);
            float w = __shfl_sync(0xffffffffu, wr, j);
            float4 v = __ldg(&h4[col * 32 + lane]);
            acc.x = fmaf(w, v.x, acc.x);
            acc.y = fmaf(w, v.y, acc.y);
            acc.z = fmaf(w, v.z, acc.z);
            acc.w = fmaf(w, v.w, acc.w);
        }
    }
    if (base < e) {
        int n = e - base;
        int2 md = (lane < n) ? d_ecolw[base + lane] : make_int2(0, 0);
        int colr = md.x;
        float wr = __int_as_float(md.y);
        for (int j = 0; j < n; ++j) {
            int col = __shfl_sync(0xffffffffu, colr, j);
            float w = __shfl_sync(0xffffffffu, wr, j);
            float4 v = __ldg(&h4[col * 32 + lane]);
            acc.x = fmaf(w, v.x, acc.x);
            acc.y = fmaf(w, v.y, acc.y);
            acc.z = fmaf(w, v.z, acc.z);
            acc.w = fmaf(w, v.w, acc.w);
        }
    }
    float4 b = *reinterpret_cast<const float4*>(&bias[lane * 4]);
    acc.x += b.x; acc.y += b.y; acc.z += b.z; acc.w += b.w;
    reinterpret_cast<float4*>(out)[warp * 32 + lane] = acc;
}

// ---------------- SpMM F=40: warp per row, scalar gathers ----------------
__global__ __launch_bounds__(256) void spmm40_kernel(
    const float* __restrict__ h, const float* __restrict__ bias,
    float* __restrict__ out, int M)
{
    const int warp = blockIdx.x * 8 + (threadIdx.x >> 5);
    const int lane = threadIdx.x & 31;
    if (warp >= M) return;
    const int s = d_rowptr[warp];
    const int e = d_rowptr[warp + 1];

    float acc0 = 0.f, acc1 = 0.f;
    int base = s;
    for (; base + 32 <= e; base += 32) {
        int2 md = d_ecolw[base + lane];
        int colr = md.x;
        float wr = __int_as_float(md.y);
#pragma unroll
        for (int j = 0; j < 32; ++j) {
            int col = __shfl_sync(0xffffffffu, colr, j);
            float w = __shfl_sync(0xffffffffu, wr, j);
            float v0 = __ldg(&h[col * FOUT + lane]);
            acc0 = fmaf(w, v0, acc0);
            if (lane < 8) {
                float v1 = __ldg(&h[col * FOUT + 32 + lane]);
                acc1 = fmaf(w, v1, acc1);
            }
        }
    }
    if (base < e) {
        int n = e - base;
        int2 md = (lane < n) ? d_ecolw[base + lane] : make_int2(0, 0);
        int colr = md.x;
        float wr = __int_as_float(md.y);
        for (int j = 0; j < n; ++j) {
            int col = __shfl_sync(0xffffffffu, colr, j);
            float w = __shfl_sync(0xffffffffu, wr, j);
            float v0 = __ldg(&h[col * FOUT + lane]);
            acc0 = fmaf(w, v0, acc0);
            if (lane < 8) {
                float v1 = __ldg(&h[col * FOUT + 32 + lane]);
                acc1 = fmaf(w, v1, acc1);
            }
        }
    }
    out[warp * FOUT + lane] = acc0 + bias[lane];
    if (lane < 8) out[warp * FOUT + 32 + lane] = acc1 + bias[32 + lane];
}

// ---------------- BatchNorm ----------------
__global__ void bnstats_kernel(const float* __restrict__ t, int layer) {
    const int f = threadIdx.x;
    float s = 0.f, s2 = 0.f;
    for (int r = blockIdx.x; r < NN; r += gridDim.x) {
        float v = t[r * FIN + f];
        s += v;
        s2 = fmaf(v, v, s2);
    }
    atomicAdd(&d_sum[layer][f], s);
    atomicAdd(&d_sumsq[layer][f], s2);
}

__global__ void bnfin_kernel(const float* __restrict__ g, const float* __restrict__ be, int layer) {
    const int f = threadIdx.x;
    const float invN = 1.f / (float)NN;
    float mean = d_sum[layer][f] * invN;
    float var = d_sumsq[layer][f] * invN - mean * mean;
    float rstd = rsqrtf(var + BN_EPS);
    float sc = g[f] * rstd;
    d_scale[layer][f] = sc;
    d_shift[layer][f] = be[f] - mean * sc;
}

// ---------------- launch ----------------
extern "C" void kernel_launch(void* const* d_in, const int* in_sizes, int n_in,
                              void* d_out, int out_size)
{
    const float* x   = (const float*)d_in[0];
    const int*   er  = (const int*)d_in[1];
    const int*   ec  = (const int*)d_in[2];
    const float* ew  = (const float*)d_in[3];
    const float* W0  = (const float*)d_in[4];
    const float* b0  = (const float*)d_in[5];
    const float* g0  = (const float*)d_in[6];
    const float* be0 = (const float*)d_in[7];
    const float* W1  = (const float*)d_in[8];
    const float* b1  = (const float*)d_in[9];
    const float* g1  = (const float*)d_in[10];
    const float* be1 = (const float*)d_in[11];
    const float* W2  = (const float*)d_in[12];
    const float* b2  = (const float*)d_in[13];
    float* out = (float*)d_out;

    const int M = in_sizes[0] / FIN;
    const int E = in_sizes[1];

    float* t0; cudaGetSymbolAddress((void**)&t0, d_t0);
    float* t1; cudaGetSymbolAddress((void**)&t1, d_t1);
    float* t2; cudaGetSymbolAddress((void**)&t2, d_t2);

    // CSR build
    zero_kernel<<<(NN + 255) / 256, 256>>>();
    hist_kernel<<<(E + 255) / 256, 256>>>(er, E);
    scan_kernel<<<1, 1024>>>(M);
    scatter_kernel<<<(E + 255) / 256, 256>>>(er, ec, ew, E);

    const int g128 = (M + 127) / 128;
    const int gsp  = (M + 7) / 8;

    // layer 0
    gemm128_kernel<false><<<g128, 256>>>(x, W0, t0, 0, M);
    spmm128_kernel<<<gsp, 256>>>(t0, b0, t1, M);
    bnstats_kernel<<<512, 128>>>(t1, 0);
    bnfin_kernel<<<1, 128>>>(g0, be0, 0);

    // layer 1
    gemm128_kernel<true><<<g128, 256>>>(t1, W1, t0, 0, M);
    spmm128_kernel<<<gsp, 256>>>(t0, b1, t1, M);
    bnstats_kernel<<<512, 128>>>(t1, 1);
    bnfin_kernel<<<1, 128>>>(g1, be1, 1);

    // layer 2
    gemm40_kernel<<<(M + 63) / 64, dim3(32, 8)>>>(t1, W2, t2, 1, M);
    spmm40_kernel<<<gsp, 256>>>(t2, b2, out, M);
}

// round 5
// speedup vs baseline: 1.4317x; 1.0688x over previous
#include <cuda_runtime.h>
#include <cuda_bf16.h>
#include <cstdint>

#define NN 50000
#define FIN 128
#define FOUT 40
#define EMAX 1600000
#define BN_EPS 1e-5f

// ---------------- device scratch ----------------
__device__ float d_t0[NN * FIN];
__device__ float d_t1[NN * FIN];
__device__ float d_t2[NN * FOUT + 64];
__device__ int2  d_ecolw[EMAX];
__device__ int   d_epos[EMAX];
__device__ int   d_counts[NN];
__device__ int   d_rowptr[NN + 1];
__device__ float d_sum[2][FIN];
__device__ float d_sumsq[2][FIN];
__device__ float d_scale[2][FIN];
__device__ float d_shift[2][FIN];

// ---------------- CSR build ----------------
__global__ void zero_kernel() {
    int i = blockIdx.x * blockDim.x + threadIdx.x;
    if (i < NN) d_counts[i] = 0;
    if (i < FIN) {
        d_sum[0][i] = 0.f; d_sum[1][i] = 0.f;
        d_sumsq[0][i] = 0.f; d_sumsq[1][i] = 0.f;
    }
}

__global__ void hist_kernel(const int* __restrict__ er, int E) {
    int i = blockIdx.x * blockDim.x + threadIdx.x;
    int e = i * 4;
    if (e + 4 <= E) {
        int4 r = *reinterpret_cast<const int4*>(&er[e]);
        int4 p;
        p.x = atomicAdd(&d_counts[r.x], 1);
        p.y = atomicAdd(&d_counts[r.y], 1);
        p.z = atomicAdd(&d_counts[r.z], 1);
        p.w = atomicAdd(&d_counts[r.w], 1);
        *reinterpret_cast<int4*>(&d_epos[e]) = p;
    } else {
        for (; e < E; ++e) d_epos[e] = atomicAdd(&d_counts[er[e]], 1);
    }
}

__global__ void scan_kernel(int Nn) {
    __shared__ int ssum[1024];
    int t = threadIdx.x;
    int chunk = (Nn + 1023) >> 10;
    int base = t * chunk;
    int s = 0;
    for (int i = 0; i < chunk; ++i) {
        int idx = base + i;
        if (idx < Nn) s += d_counts[idx];
    }
    ssum[t] = s;
    __syncthreads();
    for (int off = 1; off < 1024; off <<= 1) {
        int v = (t >= off) ? ssum[t - off] : 0;
        __syncthreads();
        ssum[t] += v;
        __syncthreads();
    }
    int run = (t > 0) ? ssum[t - 1] : 0;
    for (int i = 0; i < chunk; ++i) {
        int idx = base + i;
        if (idx < Nn) {
            d_rowptr[idx] = run;
            run += d_counts[idx];
        }
    }
    if (t == 1023) d_rowptr[Nn] = run;
}

__global__ void scatter_kernel(const int* __restrict__ er, const int* __restrict__ ec,
                               const float* __restrict__ ew, int E) {
    int i = blockIdx.x * blockDim.x + threadIdx.x;
    int e = i * 4;
    if (e + 4 <= E) {
        int4 r = *reinterpret_cast<const int4*>(&er[e]);
        int4 c = *reinterpret_cast<const int4*>(&ec[e]);
        float4 w = *reinterpret_cast<const float4*>(&ew[e]);
        int4 p = *reinterpret_cast<const int4*>(&d_epos[e]);
        d_ecolw[d_rowptr[r.x] + p.x] = make_int2(c.x, __float_as_int(w.x));
        d_ecolw[d_rowptr[r.y] + p.y] = make_int2(c.y, __float_as_int(w.y));
        d_ecolw[d_rowptr[r.z] + p.z] = make_int2(c.z, __float_as_int(w.z));
        d_ecolw[d_rowptr[r.w] + p.w] = make_int2(c.w, __float_as_int(w.w));
    } else {
        for (; e < E; ++e) {
            int pos = d_rowptr[er[e]] + d_epos[e];
            d_ecolw[pos] = make_int2(ec[e], __float_as_int(ew[e]));
        }
    }
}

// ---------------- 3xTF32 helpers ----------------
__device__ __forceinline__ void tf32_split(float a, uint32_t& hi, uint32_t& lo) {
    asm("cvt.rna.tf32.f32 %0, %1;" : "=r"(hi) : "f"(a));
    float r = a - __uint_as_float(hi);
    asm("cvt.rna.tf32.f32 %0, %1;" : "=r"(lo) : "f"(r));
}

__device__ __forceinline__ void mma_tf32(float* c, const uint32_t* a, uint32_t b0, uint32_t b1) {
    asm volatile("mma.sync.aligned.m16n8k8.row.col.f32.tf32.tf32.f32 "
        "{%0,%1,%2,%3}, {%4,%5,%6,%7}, {%8,%9}, {%0,%1,%2,%3};"
        : "+f"(c[0]), "+f"(c[1]), "+f"(c[2]), "+f"(c[3])
        : "r"(a[0]), "r"(a[1]), "r"(a[2]), "r"(a[3]), "r"(b0), "r"(b1));
}

// ---------------- GEMM 128x128 via 3xTF32 tensor cores ----------------
// Block 128x128, 256 threads = 8 warps in 4(M)x2(N) grid; warp tile 32x64.
// Each warp: 2 M-tiles (m16) x 8 N-tiles (n8), k-steps of 8.
template <bool BN>
__global__ __launch_bounds__(256) void gemm128_kernel(
    const float* __restrict__ X, const float* __restrict__ W,
    float* __restrict__ out, int layer, int M)
{
    __shared__ float Xs[128][36];   // [row][k-chunk], stride 36 (mod 32 == 4)
    __shared__ float Ws[32][136];   // [k][col], stride 136 (mod 32 == 8)

    const int tid = threadIdx.x;
    const int lane = tid & 31;
    const int warp = tid >> 5;
    const int gid = lane >> 2;      // 0..7
    const int tig = lane & 3;       // 0..3
    const int wm = warp >> 1;       // 0..3  (M position)
    const int wn = warp & 1;        // 0..1  (N position)
    const int row0 = blockIdx.x * 128;

    float c[2][8][4];
#pragma unroll
    for (int mt = 0; mt < 2; ++mt)
#pragma unroll
        for (int nt = 0; nt < 8; ++nt)
#pragma unroll
            for (int q = 0; q < 4; ++q) c[mt][nt][q] = 0.f;

    for (int kt = 0; kt < 4; ++kt) {
        const int k0 = kt * 32;
        // W chunk: rows k0..k0+31, 128 cols
#pragma unroll
        for (int l = 0; l < 4; ++l) {
            int idx = tid + 256 * l;
            int kk = idx >> 5;
            int c4 = idx & 31;
            float4 v = *reinterpret_cast<const float4*>(&W[(k0 + kk) * 128 + c4 * 4]);
            *reinterpret_cast<float4*>(&Ws[kk][c4 * 4]) = v;
        }
        // X chunk (+ optional BN+ReLU)
#pragma unroll
        for (int l = 0; l < 4; ++l) {
            int idx = tid + 256 * l;
            int r = idx >> 3;
            int c4 = idx & 7;
            int grow = row0 + r;
            float4 v = make_float4(0.f, 0.f, 0.f, 0.f);
            if (grow < M)
                v = *reinterpret_cast<const float4*>(&X[grow * 128 + k0 + c4 * 4]);
            if (BN) {
                int k = k0 + c4 * 4;
                v.x = fmaxf(fmaf(v.x, d_scale[layer][k + 0], d_shift[layer][k + 0]), 0.f);
                v.y = fmaxf(fmaf(v.y, d_scale[layer][k + 1], d_shift[layer][k + 1]), 0.f);
                v.z = fmaxf(fmaf(v.z, d_scale[layer][k + 2], d_shift[layer][k + 2]), 0.f);
                v.w = fmaxf(fmaf(v.w, d_scale[layer][k + 3], d_shift[layer][k + 3]), 0.f);
            }
            *reinterpret_cast<float4*>(&Xs[r][c4 * 4]) = v;
        }
        __syncthreads();

#pragma unroll
        for (int ks = 0; ks < 32; ks += 8) {
            // A fragments (hi/lo) for both M-tiles
            uint32_t ahi[2][4], alo[2][4];
#pragma unroll
            for (int mt = 0; mt < 2; ++mt) {
                int rb = wm * 32 + mt * 16;
                float a0 = Xs[rb + gid][ks + tig];
                float a1 = Xs[rb + gid + 8][ks + tig];
                float a2 = Xs[rb + gid][ks + tig + 4];
                float a3 = Xs[rb + gid + 8][ks + tig + 4];
                tf32_split(a0, ahi[mt][0], alo[mt][0]);
                tf32_split(a1, ahi[mt][1], alo[mt][1]);
                tf32_split(a2, ahi[mt][2], alo[mt][2]);
                tf32_split(a3, ahi[mt][3], alo[mt][3]);
            }
#pragma unroll
            for (int nt = 0; nt < 8; ++nt) {
                int ncol = wn * 64 + nt * 8 + gid;
                float b0f = Ws[ks + tig][ncol];
                float b1f = Ws[ks + tig + 4][ncol];
                uint32_t bh0, bl0, bh1, bl1;
                tf32_split(b0f, bh0, bl0);
                tf32_split(b1f, bh1, bl1);
#pragma unroll
                for (int mt = 0; mt < 2; ++mt) {
                    mma_tf32(c[mt][nt], ahi[mt], bh0, bh1);   // hi*hi
                    mma_tf32(c[mt][nt], alo[mt], bh0, bh1);   // lo*hi
                    mma_tf32(c[mt][nt], ahi[mt], bl0, bl1);   // hi*lo
                }
            }
        }
        __syncthreads();
    }

    // Epilogue: c0,c1 -> (row, 2t..2t+1); c2,c3 -> (row+8, ...)
#pragma unroll
    for (int mt = 0; mt < 2; ++mt) {
#pragma unroll
        for (int nt = 0; nt < 8; ++nt) {
            int col = wn * 64 + nt * 8 + 2 * tig;
            int r0 = row0 + wm * 32 + mt * 16 + gid;
            if (r0 < M)
                *reinterpret_cast<float2*>(&out[r0 * 128 + col]) =
                    make_float2(c[mt][nt][0], c[mt][nt][1]);
            if (r0 + 8 < M)
                *reinterpret_cast<float2*>(&out[(r0 + 8) * 128 + col]) =
                    make_float2(c[mt][nt][2], c[mt][nt][3]);
        }
    }
}

// ---------------- GEMM F=40 (final layer, fp32) ----------------
__global__ __launch_bounds__(256) void gemm40_kernel(
    const float* __restrict__ X, const float* __restrict__ W,
    float* __restrict__ out, int layer, int M)
{
    constexpr int F = FOUT;
    __shared__ float Xs[64][64];
    __shared__ float Ws[64][F];

    const int tx = threadIdx.x;
    const int ty = threadIdx.y;
    const int tid = ty * 32 + tx;
    const int row0 = blockIdx.x * 64;

    float acc[8][2];
#pragma unroll
    for (int i = 0; i < 8; ++i) { acc[i][0] = 0.f; acc[i][1] = 0.f; }

    for (int kt = 0; kt < 2; ++kt) {
        const int k0 = kt * 64;
        {
            const int nv4 = 64 * F / 4;
            for (int idx = tid; idx < nv4; idx += 256) {
                int r = idx / (F / 4);
                int c4 = idx % (F / 4);
                float4 v = *reinterpret_cast<const float4*>(&W[(k0 + r) * F + c4 * 4]);
                *reinterpret_cast<float4*>(&Ws[r][c4 * 4]) = v;
            }
        }
        {
#pragma unroll
            for (int l = 0; l < 4; ++l) {
                int idx = tid + 256 * l;
                int r = idx >> 4;
                int c4 = idx & 15;
                int grow = row0 + r;
                float4 v = make_float4(0.f, 0.f, 0.f, 0.f);
                if (grow < M)
                    v = *reinterpret_cast<const float4*>(&X[grow * FIN + k0 + c4 * 4]);
                int k = k0 + c4 * 4;
                v.x = fmaxf(fmaf(v.x, d_scale[layer][k + 0], d_shift[layer][k + 0]), 0.f);
                v.y = fmaxf(fmaf(v.y, d_scale[layer][k + 1], d_shift[layer][k + 1]), 0.f);
                v.z = fmaxf(fmaf(v.z, d_scale[layer][k + 2], d_shift[layer][k + 2]), 0.f);
                v.w = fmaxf(fmaf(v.w, d_scale[layer][k + 3], d_shift[layer][k + 3]), 0.f);
                *reinterpret_cast<float4*>(&Xs[r][c4 * 4]) = v;
            }
        }
        __syncthreads();

#pragma unroll 4
        for (int kk = 0; kk < 64; ++kk) {
            float b0 = Ws[kk][tx];
            float b1 = (tx < 8) ? Ws[kk][32 + tx] : 0.f;
#pragma unroll
            for (int i = 0; i < 8; ++i) {
                float a = Xs[ty + 8 * i][kk];
                acc[i][0] = fmaf(a, b0, acc[i][0]);
                acc[i][1] = fmaf(a, b1, acc[i][1]);
            }
        }
        __syncthreads();
    }

#pragma unroll
    for (int i = 0; i < 8; ++i) {
        int grow = row0 + ty + 8 * i;
        if (grow < M) {
            out[grow * F + tx] = acc[i][0];
            if (tx < 8) out[grow * F + 32 + tx] = acc[i][1];
        }
    }
}

// ---------------- SpMM F=128: warp per row, float4 gathers ----------------
__global__ __launch_bounds__(256) void spmm128_kernel(
    const float* __restrict__ h, const float* __restrict__ bias,
    float* __restrict__ out, int M)
{
    const int warp = blockIdx.x * 8 + (threadIdx.x >> 5);
    const int lane = threadIdx.x & 31;
    if (warp >= M) return;
    const int s = d_rowptr[warp];
    const int e = d_rowptr[warp + 1];
    const float4* __restrict__ h4 = reinterpret_cast<const float4*>(h);

    float4 acc = make_float4(0.f, 0.f, 0.f, 0.f);
    int base = s;
    for (; base + 32 <= e; base += 32) {
        int2 md = d_ecolw[base + lane];
        int colr = md.x;
        float wr = __int_as_float(md.y);
#pragma unroll
        for (int j = 0; j < 32; ++j) {
            int col = __shfl_sync(0xffffffffu, colr, j);
            float w = __shfl_sync(0xffffffffu, wr, j);
            float4 v = __ldg(&h4[col * 32 + lane]);
            acc.x = fmaf(w, v.x, acc.x);
            acc.y = fmaf(w, v.y, acc.y);
            acc.z = fmaf(w, v.z, acc.z);
            acc.w = fmaf(w, v.w, acc.w);
        }
    }
    if (base < e) {
        int n = e - base;
        int2 md = (lane < n) ? d_ecolw[base + lane] : make_int2(0, 0);
        int colr = md.x;
        float wr = __int_as_float(md.y);
        for (int j = 0; j < n; ++j) {
            int col = __shfl_sync(0xffffffffu, colr, j);
            float w = __shfl_sync(0xffffffffu, wr, j);
            float4 v = __ldg(&h4[col * 32 + lane]);
            acc.x = fmaf(w, v.x, acc.x);
            acc.y = fmaf(w, v.y, acc.y);
            acc.z = fmaf(w, v.z, acc.z);
            acc.w = fmaf(w, v.w, acc.w);
        }
    }
    float4 b = *reinterpret_cast<const float4*>(&bias[lane * 4]);
    acc.x += b.x; acc.y += b.y; acc.z += b.z; acc.w += b.w;
    reinterpret_cast<float4*>(out)[warp * 32 + lane] = acc;
}

// ---------------- SpMM F=40 ----------------
__global__ __launch_bounds__(256) void spmm40_kernel(
    const float* __restrict__ h, const float* __restrict__ bias,
    float* __restrict__ out, int M)
{
    const int warp = blockIdx.x * 8 + (threadIdx.x >> 5);
    const int lane = threadIdx.x & 31;
    if (warp >= M) return;
    const int s = d_rowptr[warp];
    const int e = d_rowptr[warp + 1];

    float acc0 = 0.f, acc1 = 0.f;
    int base = s;
    for (; base + 32 <= e; base += 32) {
        int2 md = d_ecolw[base + lane];
        int colr = md.x;
        float wr = __int_as_float(md.y);
#pragma unroll
        for (int j = 0; j < 32; ++j) {
            int col = __shfl_sync(0xffffffffu, colr, j);
            float w = __shfl_sync(0xffffffffu, wr, j);
            float v0 = __ldg(&h[col * FOUT + lane]);
            acc0 = fmaf(w, v0, acc0);
            if (lane < 8) {
                float v1 = __ldg(&h[col * FOUT + 32 + lane]);
                acc1 = fmaf(w, v1, acc1);
            }
        }
    }
    if (base < e) {
        int n = e - base;
        int2 md = (lane < n) ? d_ecolw[base + lane] : make_int2(0, 0);
        int colr = md.x;
        float wr = __int_as_float(md.y);
        for (int j = 0; j < n; ++j) {
            int col = __shfl_sync(0xffffffffu, colr, j);
            float w = __shfl_sync(0xffffffffu, wr, j);
            float v0 = __ldg(&h[col * FOUT + lane]);
            acc0 = fmaf(w, v0, acc0);
            if (lane < 8) {
                float v1 = __ldg(&h[col * FOUT + 32 + lane]);
                acc1 = fmaf(w, v1, acc1);
            }
        }
    }
    out[warp * FOUT + lane] = acc0 + bias[lane];
    if (lane < 8) out[warp * FOUT + 32 + lane] = acc1 + bias[32 + lane];
}

// ---------------- BatchNorm ----------------
__global__ void bnstats_kernel(const float* __restrict__ t, int layer) {
    const int f = threadIdx.x;
    float s = 0.f, s2 = 0.f;
    for (int r = blockIdx.x; r < NN; r += gridDim.x) {
        float v = t[r * FIN + f];
        s += v;
        s2 = fmaf(v, v, s2);
    }
    atomicAdd(&d_sum[layer][f], s);
    atomicAdd(&d_sumsq[layer][f], s2);
}

__global__ void bnfin_kernel(const float* __restrict__ g, const float* __restrict__ be, int layer) {
    const int f = threadIdx.x;
    const float invN = 1.f / (float)NN;
    float mean = d_sum[layer][f] * invN;
    float var = d_sumsq[layer][f] * invN - mean * mean;
    float rstd = rsqrtf(var + BN_EPS);
    float sc = g[f] * rstd;
    d_scale[layer][f] = sc;
    d_shift[layer][f] = be[f] - mean * sc;
}

// ---------------- launch ----------------
extern "C" void kernel_launch(void* const* d_in, const int* in_sizes, int n_in,
                              void* d_out, int out_size)
{
    const float* x   = (const float*)d_in[0];
    const int*   er  = (const int*)d_in[1];
    const int*   ec  = (const int*)d_in[2];
    const float* ew  = (const float*)d_in[3];
    const float* W0  = (const float*)d_in[4];
    const float* b0  = (const float*)d_in[5];
    const float* g0  = (const float*)d_in[6];
    const float* be0 = (const float*)d_in[7];
    const float* W1  = (const float*)d_in[8];
    const float* b1  = (const float*)d_in[9];
    const float* g1  = (const float*)d_in[10];
    const float* be1 = (const float*)d_in[11];
    const float* W2  = (const float*)d_in[12];
    const float* b2  = (const float*)d_in[13];
    float* out = (float*)d_out;

    const int M = in_sizes[0] / FIN;
    const int E = in_sizes[1];

    float* t0; cudaGetSymbolAddress((void**)&t0, d_t0);
    float* t1; cudaGetSymbolAddress((void**)&t1, d_t1);
    float* t2; cudaGetSymbolAddress((void**)&t2, d_t2);

    // CSR build
    zero_kernel<<<(NN + 255) / 256, 256>>>();
    const int E4 = (E + 3) / 4;
    hist_kernel<<<(E4 + 255) / 256, 256>>>(er, E);
    scan_kernel<<<1, 1024>>>(M);
    scatter_kernel<<<(E4 + 255) / 256, 256>>>(er, ec, ew, E);

    const int g128 = (M + 127) / 128;
    const int gsp  = (M + 7) / 8;

    // layer 0
    gemm128_kernel<false><<<g128, 256>>>(x, W0, t0, 0, M);
    spmm128_kernel<<<gsp, 256>>>(t0, b0, t1, M);
    bnstats_kernel<<<512, 128>>>(t1, 0);
    bnfin_kernel<<<1, 128>>>(g0, be0, 0);

    // layer 1
    gemm128_kernel<true><<<g128, 256>>>(t1, W1, t0, 0, M);
    spmm128_kernel<<<gsp, 256>>>(t0, b1, t1, M);
    bnstats_kernel<<<512, 128>>>(t1, 1);
    bnfin_kernel<<<1, 128>>>(g1, be1, 1);

    // layer 2
    gemm40_kernel<<<(M + 63) / 64, dim3(32, 8)>>>(t1, W2, t2, 1, M);
    spmm40_kernel<<<gsp, 256>>>(t2, b2, out, M);
}

// round 9
// speedup vs baseline: 1.4377x; 1.0042x over previous
#include <cuda_runtime.h>
#include <cuda_bf16.h>
#include <cstdint>

#define NN 50000
#define FIN 128
#define FOUT 40
#define EMAX 1600000
#define BN_EPS 1e-5f

// ---------------- device scratch ----------------
__device__ float d_t0[NN * FIN];
__device__ float d_t1[NN * FIN];
__device__ float d_t2[NN * FOUT + 64];
__device__ int2  d_ecolw[EMAX];
__device__ int   d_epos[EMAX];
__device__ int   d_counts[NN];
__device__ int   d_rowptr[NN + 1];
__device__ float d_sum[2][FIN];
__device__ float d_sumsq[2][FIN];

// ---------------- CSR build ----------------
__global__ void zero_kernel() {
    int i = blockIdx.x * blockDim.x + threadIdx.x;
    if (i < NN) d_counts[i] = 0;
    if (i < FIN) {
        d_sum[0][i] = 0.f; d_sum[1][i] = 0.f;
        d_sumsq[0][i] = 0.f; d_sumsq[1][i] = 0.f;
    }
}

__global__ void hist_kernel(const int* __restrict__ er, int E) {
    int i = blockIdx.x * blockDim.x + threadIdx.x;
    int e = i * 8;
    if (e + 8 <= E) {
        int4 r0 = *reinterpret_cast<const int4*>(&er[e]);
        int4 r1 = *reinterpret_cast<const int4*>(&er[e + 4]);
        int4 p0, p1;
        p0.x = atomicAdd(&d_counts[r0.x], 1);
        p0.y = atomicAdd(&d_counts[r0.y], 1);
        p0.z = atomicAdd(&d_counts[r0.z], 1);
        p0.w = atomicAdd(&d_counts[r0.w], 1);
        p1.x = atomicAdd(&d_counts[r1.x], 1);
        p1.y = atomicAdd(&d_counts[r1.y], 1);
        p1.z = atomicAdd(&d_counts[r1.z], 1);
        p1.w = atomicAdd(&d_counts[r1.w], 1);
        *reinterpret_cast<int4*>(&d_epos[e]) = p0;
        *reinterpret_cast<int4*>(&d_epos[e + 4]) = p1;
    } else {
        for (; e < E; ++e) d_epos[e] = atomicAdd(&d_counts[er[e]], 1);
    }
}

__global__ void scan_kernel(int Nn) {
    __shared__ int ssum[1024];
    int t = threadIdx.x;
    int chunk = (Nn + 1023) >> 10;
    int base = t * chunk;
    int s = 0;
    for (int i = 0; i < chunk; ++i) {
        int idx = base + i;
        if (idx < Nn) s += d_counts[idx];
    }
    ssum[t] = s;
    __syncthreads();
    for (int off = 1; off < 1024; off <<= 1) {
        int v = (t >= off) ? ssum[t - off] : 0;
        __syncthreads();
        ssum[t] += v;
        __syncthreads();
    }
    int run = (t > 0) ? ssum[t - 1] : 0;
    for (int i = 0; i < chunk; ++i) {
        int idx = base + i;
        if (idx < Nn) {
            d_rowptr[idx] = run;
            run += d_counts[idx];
        }
    }
    if (t == 1023) d_rowptr[Nn] = run;
}

__global__ void scatter_kernel(const int* __restrict__ er, const int* __restrict__ ec,
                               const float* __restrict__ ew, int E) {
    int i = blockIdx.x * blockDim.x + threadIdx.x;
    int e = i * 8;
    if (e + 8 <= E) {
        int4 r0 = *reinterpret_cast<const int4*>(&er[e]);
        int4 r1 = *reinterpret_cast<const int4*>(&er[e + 4]);
        int4 c0 = *reinterpret_cast<const int4*>(&ec[e]);
        int4 c1 = *reinterpret_cast<const int4*>(&ec[e + 4]);
        float4 w0 = *reinterpret_cast<const float4*>(&ew[e]);
        float4 w1 = *reinterpret_cast<const float4*>(&ew[e + 4]);
        int4 p0 = *reinterpret_cast<const int4*>(&d_epos[e]);
        int4 p1 = *reinterpret_cast<const int4*>(&d_epos[e + 4]);
        int b0 = d_rowptr[r0.x], b1 = d_rowptr[r0.y], b2 = d_rowptr[r0.z], b3 = d_rowptr[r0.w];
        int b4 = d_rowptr[r1.x], b5 = d_rowptr[r1.y], b6 = d_rowptr[r1.z], b7 = d_rowptr[r1.w];
        d_ecolw[b0 + p0.x] = make_int2(c0.x, __float_as_int(w0.x));
        d_ecolw[b1 + p0.y] = make_int2(c0.y, __float_as_int(w0.y));
        d_ecolw[b2 + p0.z] = make_int2(c0.z, __float_as_int(w0.z));
        d_ecolw[b3 + p0.w] = make_int2(c0.w, __float_as_int(w0.w));
        d_ecolw[b4 + p1.x] = make_int2(c1.x, __float_as_int(w1.x));
        d_ecolw[b5 + p1.y] = make_int2(c1.y, __float_as_int(w1.y));
        d_ecolw[b6 + p1.z] = make_int2(c1.z, __float_as_int(w1.z));
        d_ecolw[b7 + p1.w] = make_int2(c1.w, __float_as_int(w1.w));
    } else {
        for (; e < E; ++e) {
            int pos = d_rowptr[er[e]] + d_epos[e];
            d_ecolw[pos] = make_int2(ec[e], __float_as_int(ew[e]));
        }
    }
}

// ---------------- 3xTF32 helpers ----------------
__device__ __forceinline__ void tf32_split(float a, uint32_t& hi, uint32_t& lo) {
    asm("cvt.rna.tf32.f32 %0, %1;" : "=r"(hi) : "f"(a));
    float r = a - __uint_as_float(hi);
    asm("cvt.rna.tf32.f32 %0, %1;" : "=r"(lo) : "f"(r));
}

__device__ __forceinline__ void mma_tf32(float* c, const uint32_t* a, uint32_t b0, uint32_t b1) {
    asm volatile("mma.sync.aligned.m16n8k8.row.col.f32.tf32.tf32.f32 "
        "{%0,%1,%2,%3}, {%4,%5,%6,%7}, {%8,%9}, {%0,%1,%2,%3};"
        : "+f"(c[0]), "+f"(c[1]), "+f"(c[2]), "+f"(c[3])
        : "r"(a[0]), "r"(a[1]), "r"(a[2]), "r"(a[3]), "r"(b0), "r"(b1));
}

// ---------------- GEMM 128x128 via 3xTF32 tensor cores ----------------
// BN finalize fused into prologue: scale/shift computed from d_sum/d_sumsq.
template <bool BN>
__global__ __launch_bounds__(256) void gemm128_kernel(
    const float* __restrict__ X, const float* __restrict__ W,
    float* __restrict__ out,
    const float* __restrict__ g, const float* __restrict__ be,
    int layer, int M)
{
    __shared__ float Xs[128][36];
    __shared__ float Ws[32][136];
    __shared__ float ssc[128], ssh[128];

    const int tid = threadIdx.x;
    const int lane = tid & 31;
    const int warp = tid >> 5;
    const int gid = lane >> 2;
    const int tig = lane & 3;
    const int wm = warp >> 1;
    const int wn = warp & 1;
    const int row0 = blockIdx.x * 128;

    if (BN) {
        if (tid < 128) {
            const float invN = 1.f / (float)NN;
            float mean = d_sum[layer][tid] * invN;
            float var = d_sumsq[layer][tid] * invN - mean * mean;
            float sc = g[tid] * rsqrtf(var + BN_EPS);
            ssc[tid] = sc;
            ssh[tid] = fmaf(-mean, sc, be[tid]);
        }
        __syncthreads();
    }

    float c[2][8][4];
#pragma unroll
    for (int mt = 0; mt < 2; ++mt)
#pragma unroll
        for (int nt = 0; nt < 8; ++nt)
#pragma unroll
            for (int q = 0; q < 4; ++q) c[mt][nt][q] = 0.f;

    for (int kt = 0; kt < 4; ++kt) {
        const int k0 = kt * 32;
#pragma unroll
        for (int l = 0; l < 4; ++l) {
            int idx = tid + 256 * l;
            int kk = idx >> 5;
            int c4 = idx & 31;
            float4 v = *reinterpret_cast<const float4*>(&W[(k0 + kk) * 128 + c4 * 4]);
            *reinterpret_cast<float4*>(&Ws[kk][c4 * 4]) = v;
        }
#pragma unroll
        for (int l = 0; l < 4; ++l) {
            int idx = tid + 256 * l;
            int r = idx >> 3;
            int c4 = idx & 7;
            int grow = row0 + r;
            float4 v = make_float4(0.f, 0.f, 0.f, 0.f);
            if (grow < M)
                v = *reinterpret_cast<const float4*>(&X[grow * 128 + k0 + c4 * 4]);
            if (BN) {
                int k = k0 + c4 * 4;
                v.x = fmaxf(fmaf(v.x, ssc[k + 0], ssh[k + 0]), 0.f);
                v.y = fmaxf(fmaf(v.y, ssc[k + 1], ssh[k + 1]), 0.f);
                v.z = fmaxf(fmaf(v.z, ssc[k + 2], ssh[k + 2]), 0.f);
                v.w = fmaxf(fmaf(v.w, ssc[k + 3], ssh[k + 3]), 0.f);
            }
            *reinterpret_cast<float4*>(&Xs[r][c4 * 4]) = v;
        }
        __syncthreads();

#pragma unroll
        for (int ks = 0; ks < 32; ks += 8) {
            uint32_t ahi[2][4], alo[2][4];
#pragma unroll
            for (int mt = 0; mt < 2; ++mt) {
                int rb = wm * 32 + mt * 16;
                float a0 = Xs[rb + gid][ks + tig];
                float a1 = Xs[rb + gid + 8][ks + tig];
                float a2 = Xs[rb + gid][ks + tig + 4];
                float a3 = Xs[rb + gid + 8][ks + tig + 4];
                tf32_split(a0, ahi[mt][0], alo[mt][0]);
                tf32_split(a1, ahi[mt][1], alo[mt][1]);
                tf32_split(a2, ahi[mt][2], alo[mt][2]);
                tf32_split(a3, ahi[mt][3], alo[mt][3]);
            }
#pragma unroll
            for (int nt = 0; nt < 8; ++nt) {
                int ncol = wn * 64 + nt * 8 + gid;
                float b0f = Ws[ks + tig][ncol];
                float b1f = Ws[ks + tig + 4][ncol];
                uint32_t bh0, bl0, bh1, bl1;
                tf32_split(b0f, bh0, bl0);
                tf32_split(b1f, bh1, bl1);
#pragma unroll
                for (int mt = 0; mt < 2; ++mt) {
                    mma_tf32(c[mt][nt], ahi[mt], bh0, bh1);
                    mma_tf32(c[mt][nt], alo[mt], bh0, bh1);
                    mma_tf32(c[mt][nt], ahi[mt], bl0, bl1);
                }
            }
        }
        __syncthreads();
    }

#pragma unroll
    for (int mt = 0; mt < 2; ++mt) {
#pragma unroll
        for (int nt = 0; nt < 8; ++nt) {
            int col = wn * 64 + nt * 8 + 2 * tig;
            int r0 = row0 + wm * 32 + mt * 16 + gid;
            if (r0 < M)
                *reinterpret_cast<float2*>(&out[r0 * 128 + col]) =
                    make_float2(c[mt][nt][0], c[mt][nt][1]);
            if (r0 + 8 < M)
                *reinterpret_cast<float2*>(&out[(r0 + 8) * 128 + col]) =
                    make_float2(c[mt][nt][2], c[mt][nt][3]);
        }
    }
}

// ---------------- GEMM F=40 (final layer, fp32, BN finalize fused) ----------------
__global__ __launch_bounds__(256) void gemm40_kernel(
    const float* __restrict__ X, const float* __restrict__ W,
    float* __restrict__ out,
    const float* __restrict__ g, const float* __restrict__ be,
    int layer, int M)
{
    constexpr int F = FOUT;
    __shared__ float Xs[64][64];
    __shared__ float Ws[64][F];
    __shared__ float ssc[128], ssh[128];

    const int tx = threadIdx.x;
    const int ty = threadIdx.y;
    const int tid = ty * 32 + tx;
    const int row0 = blockIdx.x * 64;

    if (tid < 128) {
        const float invN = 1.f / (float)NN;
        float mean = d_sum[layer][tid] * invN;
        float var = d_sumsq[layer][tid] * invN - mean * mean;
        float sc = g[tid] * rsqrtf(var + BN_EPS);
        ssc[tid] = sc;
        ssh[tid] = fmaf(-mean, sc, be[tid]);
    }
    __syncthreads();

    float acc[8][2];
#pragma unroll
    for (int i = 0; i < 8; ++i) { acc[i][0] = 0.f; acc[i][1] = 0.f; }

    for (int kt = 0; kt < 2; ++kt) {
        const int k0 = kt * 64;
        {
            const int nv4 = 64 * F / 4;
            for (int idx = tid; idx < nv4; idx += 256) {
                int r = idx / (F / 4);
                int c4 = idx % (F / 4);
                float4 v = *reinterpret_cast<const float4*>(&W[(k0 + r) * F + c4 * 4]);
                *reinterpret_cast<float4*>(&Ws[r][c4 * 4]) = v;
            }
        }
        {
#pragma unroll
            for (int l = 0; l < 4; ++l) {
                int idx = tid + 256 * l;
                int r = idx >> 4;
                int c4 = idx & 15;
                int grow = row0 + r;
                float4 v = make_float4(0.f, 0.f, 0.f, 0.f);
                if (grow < M)
                    v = *reinterpret_cast<const float4*>(&X[grow * FIN + k0 + c4 * 4]);
                int k = k0 + c4 * 4;
                v.x = fmaxf(fmaf(v.x, ssc[k + 0], ssh[k + 0]), 0.f);
                v.y = fmaxf(fmaf(v.y, ssc[k + 1], ssh[k + 1]), 0.f);
                v.z = fmaxf(fmaf(v.z, ssc[k + 2], ssh[k + 2]), 0.f);
                v.w = fmaxf(fmaf(v.w, ssc[k + 3], ssh[k + 3]), 0.f);
                *reinterpret_cast<float4*>(&Xs[r][c4 * 4]) = v;
            }
        }
        __syncthreads();

#pragma unroll 4
        for (int kk = 0; kk < 64; ++kk) {
            float b0 = Ws[kk][tx];
            float b1 = (tx < 8) ? Ws[kk][32 + tx] : 0.f;
#pragma unroll
            for (int i = 0; i < 8; ++i) {
                float a = Xs[ty + 8 * i][kk];
                acc[i][0] = fmaf(a, b0, acc[i][0]);
                acc[i][1] = fmaf(a, b1, acc[i][1]);
            }
        }
        __syncthreads();
    }

#pragma unroll
    for (int i = 0; i < 8; ++i) {
        int grow = row0 + ty + 8 * i;
        if (grow < M) {
            out[grow * F + tx] = acc[i][0];
            if (tx < 8) out[grow * F + 32 + tx] = acc[i][1];
        }
    }
}

// ---------------- SpMM F=128 + fused BN stats ----------------
__global__ __launch_bounds__(256) void spmm128_kernel(
    const float* __restrict__ h, const float* __restrict__ bias,
    float* __restrict__ out, int layer, int M)
{
    __shared__ float bsum[128], bsq[128];
    const int warp = blockIdx.x * 8 + (threadIdx.x >> 5);
    const int lane = threadIdx.x & 31;
    const int tid = threadIdx.x;

    if (tid < 128) { bsum[tid] = 0.f; bsq[tid] = 0.f; }
    __syncthreads();

    float4 acc = make_float4(0.f, 0.f, 0.f, 0.f);
    if (warp < M) {
        const int s = d_rowptr[warp];
        const int e = d_rowptr[warp + 1];
        const float4* __restrict__ h4 = reinterpret_cast<const float4*>(h);
        int base = s;
        for (; base + 32 <= e; base += 32) {
            int2 md = d_ecolw[base + lane];
            int colr = md.x;
            float wr = __int_as_float(md.y);
#pragma unroll
            for (int j = 0; j < 32; ++j) {
                int col = __shfl_sync(0xffffffffu, colr, j);
                float w = __shfl_sync(0xffffffffu, wr, j);
                float4 v = __ldg(&h4[col * 32 + lane]);
                acc.x = fmaf(w, v.x, acc.x);
                acc.y = fmaf(w, v.y, acc.y);
                acc.z = fmaf(w, v.z, acc.z);
                acc.w = fmaf(w, v.w, acc.w);
            }
        }
        if (base < e) {
            int n = e - base;
            int2 md = (lane < n) ? d_ecolw[base + lane] : make_int2(0, 0);
            int colr = md.x;
            float wr = __int_as_float(md.y);
            for (int j = 0; j < n; ++j) {
                int col = __shfl_sync(0xffffffffu, colr, j);
                float w = __shfl_sync(0xffffffffu, wr, j);
                float4 v = __ldg(&h4[col * 32 + lane]);
                acc.x = fmaf(w, v.x, acc.x);
                acc.y = fmaf(w, v.y, acc.y);
                acc.z = fmaf(w, v.z, acc.z);
                acc.w = fmaf(w, v.w, acc.w);
            }
        }
        float4 b = *reinterpret_cast<const float4*>(&bias[lane * 4]);
        acc.x += b.x; acc.y += b.y; acc.z += b.z; acc.w += b.w;
        reinterpret_cast<float4*>(out)[warp * 32 + lane] = acc;

        // accumulate block-local BN stats
        int f = lane * 4;
        atomicAdd(&bsum[f + 0], acc.x);
        atomicAdd(&bsum[f + 1], acc.y);
        atomicAdd(&bsum[f + 2], acc.z);
        atomicAdd(&bsum[f + 3], acc.w);
        atomicAdd(&bsq[f + 0], acc.x * acc.x);
        atomicAdd(&bsq[f + 1], acc.y * acc.y);
        atomicAdd(&bsq[f + 2], acc.z * acc.z);
        atomicAdd(&bsq[f + 3], acc.w * acc.w);
    }
    __syncthreads();
    if (tid < 128) {
        atomicAdd(&d_sum[layer][tid], bsum[tid]);
        atomicAdd(&d_sumsq[layer][tid], bsq[tid]);
    }
}

// ---------------- SpMM F=40 ----------------
__global__ __launch_bounds__(256) void spmm40_kernel(
    const float* __restrict__ h, const float* __restrict__ bias,
    float* __restrict__ out, int M)
{
    const int warp = blockIdx.x * 8 + (threadIdx.x >> 5);
    const int lane = threadIdx.x & 31;
    if (warp >= M) return;
    const int s = d_rowptr[warp];
    const int e = d_rowptr[warp + 1];

    float acc0 = 0.f, acc1 = 0.f;
    int base = s;
    for (; base + 32 <= e; base += 32) {
        int2 md = d_ecolw[base + lane];
        int colr = md.x;
        float wr = __int_as_float(md.y);
#pragma unroll
        for (int j = 0; j < 32; ++j) {
            int col = __shfl_sync(0xffffffffu, colr, j);
            float w = __shfl_sync(0xffffffffu, wr, j);
            float v0 = __ldg(&h[col * FOUT + lane]);
            acc0 = fmaf(w, v0, acc0);
            if (lane < 8) {
                float v1 = __ldg(&h[col * FOUT + 32 + lane]);
                acc1 = fmaf(w, v1, acc1);
            }
        }
    }
    if (base < e) {
        int n = e - base;
        int2 md = (lane < n) ? d_ecolw[base + lane] : make_int2(0, 0);
        int colr = md.x;
        float wr = __int_as_float(md.y);
        for (int j = 0; j < n; ++j) {
            int col = __shfl_sync(0xffffffffu, colr, j);
            float w = __shfl_sync(0xffffffffu, wr, j);
            float v0 = __ldg(&h[col * FOUT + lane]);
            acc0 = fmaf(w, v0, acc0);
            if (lane < 8) {
                float v1 = __ldg(&h[col * FOUT + 32 + lane]);
                acc1 = fmaf(w, v1, acc1);
            }
        }
    }
    out[warp * FOUT + lane] = acc0 + bias[lane];
    if (lane < 8) out[warp * FOUT + 32 + lane] = acc1 + bias[32 + lane];
}

// ---------------- launch ----------------
extern "C" void kernel_launch(void* const* d_in, const int* in_sizes, int n_in,
                              void* d_out, int out_size)
{
    const float* x   = (const float*)d_in[0];
    const int*   er  = (const int*)d_in[1];
    const int*   ec  = (const int*)d_in[2];
    const float* ew  = (const float*)d_in[3];
    const float* W0  = (const float*)d_in[4];
    const float* b0  = (const float*)d_in[5];
    const float* g0  = (const float*)d_in[6];
    const float* be0 = (const float*)d_in[7];
    const float* W1  = (const float*)d_in[8];
    const float* b1  = (const float*)d_in[9];
    const float* g1  = (const float*)d_in[10];
    const float* be1 = (const float*)d_in[11];
    const float* W2  = (const float*)d_in[12];
    const float* b2  = (const float*)d_in[13];
    float* out = (float*)d_out;

    const int M = in_sizes[0] / FIN;
    const int E = in_sizes[1];

    float* t0; cudaGetSymbolAddress((void**)&t0, d_t0);
    float* t1; cudaGetSymbolAddress((void**)&t1, d_t1);
    float* t2; cudaGetSymbolAddress((void**)&t2, d_t2);

    // CSR build
    zero_kernel<<<(NN + 255) / 256, 256>>>();
    const int E8 = (E + 7) / 8;
    hist_kernel<<<(E8 + 255) / 256, 256>>>(er, E);
    scan_kernel<<<1, 1024>>>(M);
    scatter_kernel<<<(E8 + 255) / 256, 256>>>(er, ec, ew, E);

    const int g128 = (M + 127) / 128;
    const int gsp  = (M + 7) / 8;

    // layer 0
    gemm128_kernel<false><<<g128, 256>>>(x, W0, t0, nullptr, nullptr, 0, M);
    spmm128_kernel<<<gsp, 256>>>(t0, b0, t1, 0, M);

    // layer 1 (BN finalize of layer-0 stats fused into gemm prologue)
    gemm128_kernel<true><<<g128, 256>>>(t1, W1, t0, g0, be0, 0, M);
    spmm128_kernel<<<gsp, 256>>>(t0, b1, t1, 1, M);

    // layer 2 (BN finalize of layer-1 stats fused into gemm40 prologue)
    gemm40_kernel<<<(M + 63) / 64, dim3(32, 8)>>>(t1, W2, t2, g1, be1, 1, M);
    spmm40_kernel<<<gsp, 256>>>(t2, b2, out, M);
}

// round 11
// speedup vs baseline: 1.6135x; 1.1223x over previous
#include <cuda_runtime.h>
#include <cuda_bf16.h>
#include <cuda_fp16.h>
#include <cstdint>

#define NN 50000
#define FIN 128
#define FOUT 40
#define EMAX 1600000
#define BN_EPS 1e-5f

// ---------------- device scratch ----------------
__device__ int2  d_t0h[NN * 32];            // fp16 gemm output (128 halfs = 32 int2 per row)
__device__ float d_t1[NN * FIN];            // spmm output (fp32 activations)
__device__ float d_t2[NN * FOUT + 64];
__device__ int2  d_ecolw[EMAX];
__device__ int   d_epos[EMAX];
__device__ int   d_counts[NN];
__device__ int   d_rowptr[NN + 1];
__device__ float d_sum[2][FIN];
__device__ float d_sumsq[2][FIN];

// ---------------- CSR build ----------------
__global__ void zero_kernel() {
    int i = blockIdx.x * blockDim.x + threadIdx.x;
    if (i < NN) d_counts[i] = 0;
    if (i < FIN) {
        d_sum[0][i] = 0.f; d_sum[1][i] = 0.f;
        d_sumsq[0][i] = 0.f; d_sumsq[1][i] = 0.f;
    }
}

__global__ void hist_kernel(const int* __restrict__ er, int E) {
    int i = blockIdx.x * blockDim.x + threadIdx.x;
    int e = i * 8;
    if (e + 8 <= E) {
        int4 r0 = *reinterpret_cast<const int4*>(&er[e]);
        int4 r1 = *reinterpret_cast<const int4*>(&er[e + 4]);
        int4 p0, p1;
        p0.x = atomicAdd(&d_counts[r0.x], 1);
        p0.y = atomicAdd(&d_counts[r0.y], 1);
        p0.z = atomicAdd(&d_counts[r0.z], 1);
        p0.w = atomicAdd(&d_counts[r0.w], 1);
        p1.x = atomicAdd(&d_counts[r1.x], 1);
        p1.y = atomicAdd(&d_counts[r1.y], 1);
        p1.z = atomicAdd(&d_counts[r1.z], 1);
        p1.w = atomicAdd(&d_counts[r1.w], 1);
        *reinterpret_cast<int4*>(&d_epos[e]) = p0;
        *reinterpret_cast<int4*>(&d_epos[e + 4]) = p1;
    } else {
        for (; e < E; ++e) d_epos[e] = atomicAdd(&d_counts[er[e]], 1);
    }
}

__global__ void scan_kernel(int Nn) {
    __shared__ int ssum[1024];
    int t = threadIdx.x;
    int chunk = (Nn + 1023) >> 10;
    int base = t * chunk;
    int s = 0;
    for (int i = 0; i < chunk; ++i) {
        int idx = base + i;
        if (idx < Nn) s += d_counts[idx];
    }
    ssum[t] = s;
    __syncthreads();
    for (int off = 1; off < 1024; off <<= 1) {
        int v = (t >= off) ? ssum[t - off] : 0;
        __syncthreads();
        ssum[t] += v;
        __syncthreads();
    }
    int run = (t > 0) ? ssum[t - 1] : 0;
    for (int i = 0; i < chunk; ++i) {
        int idx = base + i;
        if (idx < Nn) {
            d_rowptr[idx] = run;
            run += d_counts[idx];
        }
    }
    if (t == 1023) d_rowptr[Nn] = run;
}

__global__ void scatter_kernel(const int* __restrict__ er, const int* __restrict__ ec,
                               const float* __restrict__ ew, int E) {
    int i = blockIdx.x * blockDim.x + threadIdx.x;
    int e = i * 8;
    if (e + 8 <= E) {
        int4 r0 = *reinterpret_cast<const int4*>(&er[e]);
        int4 r1 = *reinterpret_cast<const int4*>(&er[e + 4]);
        int4 c0 = *reinterpret_cast<const int4*>(&ec[e]);
        int4 c1 = *reinterpret_cast<const int4*>(&ec[e + 4]);
        float4 w0 = *reinterpret_cast<const float4*>(&ew[e]);
        float4 w1 = *reinterpret_cast<const float4*>(&ew[e + 4]);
        int4 p0 = *reinterpret_cast<const int4*>(&d_epos[e]);
        int4 p1 = *reinterpret_cast<const int4*>(&d_epos[e + 4]);
        int b0 = d_rowptr[r0.x], b1 = d_rowptr[r0.y], b2 = d_rowptr[r0.z], b3 = d_rowptr[r0.w];
        int b4 = d_rowptr[r1.x], b5 = d_rowptr[r1.y], b6 = d_rowptr[r1.z], b7 = d_rowptr[r1.w];
        d_ecolw[b0 + p0.x] = make_int2(c0.x, __float_as_int(w0.x));
        d_ecolw[b1 + p0.y] = make_int2(c0.y, __float_as_int(w0.y));
        d_ecolw[b2 + p0.z] = make_int2(c0.z, __float_as_int(w0.z));
        d_ecolw[b3 + p0.w] = make_int2(c0.w, __float_as_int(w0.w));
        d_ecolw[b4 + p1.x] = make_int2(c1.x, __float_as_int(w1.x));
        d_ecolw[b5 + p1.y] = make_int2(c1.y, __float_as_int(w1.y));
        d_ecolw[b6 + p1.z] = make_int2(c1.z, __float_as_int(w1.z));
        d_ecolw[b7 + p1.w] = make_int2(c1.w, __float_as_int(w1.w));
    } else {
        for (; e < E; ++e) {
            int pos = d_rowptr[er[e]] + d_epos[e];
            d_ecolw[pos] = make_int2(ec[e], __float_as_int(ew[e]));
        }
    }
}

// ---------------- 3xTF32 helpers ----------------
__device__ __forceinline__ void tf32_split(float a, uint32_t& hi, uint32_t& lo) {
    asm("cvt.rna.tf32.f32 %0, %1;" : "=r"(hi) : "f"(a));
    float r = a - __uint_as_float(hi);
    asm("cvt.rna.tf32.f32 %0, %1;" : "=r"(lo) : "f"(r));
}

__device__ __forceinline__ void mma_tf32(float* c, const uint32_t* a, uint32_t b0, uint32_t b1) {
    asm volatile("mma.sync.aligned.m16n8k8.row.col.f32.tf32.tf32.f32 "
        "{%0,%1,%2,%3}, {%4,%5,%6,%7}, {%8,%9}, {%0,%1,%2,%3};"
        : "+f"(c[0]), "+f"(c[1]), "+f"(c[2]), "+f"(c[3])
        : "r"(a[0]), "r"(a[1]), "r"(a[2]), "r"(a[3]), "r"(b0), "r"(b1));
}

// ---------------- GEMM 128x128 via 3xTF32, pre-split operands, fp16 output ----------------
template <bool BN>
__global__ __launch_bounds__(256) void gemm128_kernel(
    const float* __restrict__ X, const float* __restrict__ W,
    __half2* __restrict__ outh,
    const float* __restrict__ g, const float* __restrict__ be,
    int layer, int M)
{
    __shared__ uint32_t Xhi[128][36], Xlo[128][36];
    __shared__ uint32_t Whi[32][136], Wlo[32][136];
    __shared__ float ssc[128], ssh[128];

    const int tid = threadIdx.x;
    const int lane = tid & 31;
    const int warp = tid >> 5;
    const int gid = lane >> 2;
    const int tig = lane & 3;
    const int wm = warp >> 1;
    const int wn = warp & 1;
    const int row0 = blockIdx.x * 128;

    if (BN) {
        if (tid < 128) {
            const float invN = 1.f / (float)NN;
            float mean = d_sum[layer][tid] * invN;
            float var = d_sumsq[layer][tid] * invN - mean * mean;
            float sc = g[tid] * rsqrtf(var + BN_EPS);
            ssc[tid] = sc;
            ssh[tid] = fmaf(-mean, sc, be[tid]);
        }
        __syncthreads();
    }

    float c[2][8][4];
#pragma unroll
    for (int mt = 0; mt < 2; ++mt)
#pragma unroll
        for (int nt = 0; nt < 8; ++nt)
#pragma unroll
            for (int q = 0; q < 4; ++q) c[mt][nt][q] = 0.f;

    for (int kt = 0; kt < 4; ++kt) {
        const int k0 = kt * 32;
        // W chunk: load + split
#pragma unroll
        for (int l = 0; l < 4; ++l) {
            int idx = tid + 256 * l;
            int kk = idx >> 5;
            int c4 = idx & 31;
            float4 v = *reinterpret_cast<const float4*>(&W[(k0 + kk) * 128 + c4 * 4]);
            uint4 h, lo;
            tf32_split(v.x, h.x, lo.x);
            tf32_split(v.y, h.y, lo.y);
            tf32_split(v.z, h.z, lo.z);
            tf32_split(v.w, h.w, lo.w);
            *reinterpret_cast<uint4*>(&Whi[kk][c4 * 4]) = h;
            *reinterpret_cast<uint4*>(&Wlo[kk][c4 * 4]) = lo;
        }
        // X chunk: load (+BN) + split
#pragma unroll
        for (int l = 0; l < 4; ++l) {
            int idx = tid + 256 * l;
            int r = idx >> 3;
            int c4 = idx & 7;
            int grow = row0 + r;
            float4 v = make_float4(0.f, 0.f, 0.f, 0.f);
            if (grow < M)
                v = *reinterpret_cast<const float4*>(&X[grow * 128 + k0 + c4 * 4]);
            if (BN) {
                int k = k0 + c4 * 4;
                v.x = fmaxf(fmaf(v.x, ssc[k + 0], ssh[k + 0]), 0.f);
                v.y = fmaxf(fmaf(v.y, ssc[k + 1], ssh[k + 1]), 0.f);
                v.z = fmaxf(fmaf(v.z, ssc[k + 2], ssh[k + 2]), 0.f);
                v.w = fmaxf(fmaf(v.w, ssc[k + 3], ssh[k + 3]), 0.f);
            }
            uint4 h, lo;
            tf32_split(v.x, h.x, lo.x);
            tf32_split(v.y, h.y, lo.y);
            tf32_split(v.z, h.z, lo.z);
            tf32_split(v.w, h.w, lo.w);
            *reinterpret_cast<uint4*>(&Xhi[r][c4 * 4]) = h;
            *reinterpret_cast<uint4*>(&Xlo[r][c4 * 4]) = lo;
        }
        __syncthreads();

#pragma unroll
        for (int ks = 0; ks < 32; ks += 8) {
            uint32_t ahi[2][4], alo[2][4];
#pragma unroll
            for (int mt = 0; mt < 2; ++mt) {
                int rb = wm * 32 + mt * 16;
                ahi[mt][0] = Xhi[rb + gid][ks + tig];
                ahi[mt][1] = Xhi[rb + gid + 8][ks + tig];
                ahi[mt][2] = Xhi[rb + gid][ks + tig + 4];
                ahi[mt][3] = Xhi[rb + gid + 8][ks + tig + 4];
                alo[mt][0] = Xlo[rb + gid][ks + tig];
                alo[mt][1] = Xlo[rb + gid + 8][ks + tig];
                alo[mt][2] = Xlo[rb + gid][ks + tig + 4];
                alo[mt][3] = Xlo[rb + gid + 8][ks + tig + 4];
            }
#pragma unroll
            for (int nt = 0; nt < 8; ++nt) {
                int ncol = wn * 64 + nt * 8 + gid;
                uint32_t bh0 = Whi[ks + tig][ncol];
                uint32_t bh1 = Whi[ks + tig + 4][ncol];
                uint32_t bl0 = Wlo[ks + tig][ncol];
                uint32_t bl1 = Wlo[ks + tig + 4][ncol];
#pragma unroll
                for (int mt = 0; mt < 2; ++mt) {
                    mma_tf32(c[mt][nt], ahi[mt], bh0, bh1);
                    mma_tf32(c[mt][nt], alo[mt], bh0, bh1);
                    mma_tf32(c[mt][nt], ahi[mt], bl0, bl1);
                }
            }
        }
        __syncthreads();
    }

    // fp16 epilogue: half index == feature index (linear row layout)
#pragma unroll
    for (int mt = 0; mt < 2; ++mt) {
#pragma unroll
        for (int nt = 0; nt < 8; ++nt) {
            int col = wn * 64 + nt * 8 + 2 * tig;   // even feature
            int r0 = row0 + wm * 32 + mt * 16 + gid;
            if (r0 < M)
                outh[r0 * 64 + (col >> 1)] =
                    __float22half2_rn(make_float2(c[mt][nt][0], c[mt][nt][1]));
            if (r0 + 8 < M)
                outh[(r0 + 8) * 64 + (col >> 1)] =
                    __float22half2_rn(make_float2(c[mt][nt][2], c[mt][nt][3]));
        }
    }
}

// ---------------- GEMM F=40 (final layer, fp32, BN finalize fused) ----------------
__global__ __launch_bounds__(256) void gemm40_kernel(
    const float* __restrict__ X, const float* __restrict__ W,
    float* __restrict__ out,
    const float* __restrict__ g, const float* __restrict__ be,
    int layer, int M)
{
    constexpr int F = FOUT;
    __shared__ float Xs[64][64];
    __shared__ float Ws[64][F];
    __shared__ float ssc[128], ssh[128];

    const int tx = threadIdx.x;
    const int ty = threadIdx.y;
    const int tid = ty * 32 + tx;
    const int row0 = blockIdx.x * 64;

    if (tid < 128) {
        const float invN = 1.f / (float)NN;
        float mean = d_sum[layer][tid] * invN;
        float var = d_sumsq[layer][tid] * invN - mean * mean;
        float sc = g[tid] * rsqrtf(var + BN_EPS);
        ssc[tid] = sc;
        ssh[tid] = fmaf(-mean, sc, be[tid]);
    }
    __syncthreads();

    float acc[8][2];
#pragma unroll
    for (int i = 0; i < 8; ++i) { acc[i][0] = 0.f; acc[i][1] = 0.f; }

    for (int kt = 0; kt < 2; ++kt) {
        const int k0 = kt * 64;
        {
            const int nv4 = 64 * F / 4;
            for (int idx = tid; idx < nv4; idx += 256) {
                int r = idx / (F / 4);
                int c4 = idx % (F / 4);
                float4 v = *reinterpret_cast<const float4*>(&W[(k0 + r) * F + c4 * 4]);
                *reinterpret_cast<float4*>(&Ws[r][c4 * 4]) = v;
            }
        }
        {
#pragma unroll
            for (int l = 0; l < 4; ++l) {
                int idx = tid + 256 * l;
                int r = idx >> 4;
                int c4 = idx & 15;
                int grow = row0 + r;
                float4 v = make_float4(0.f, 0.f, 0.f, 0.f);
                if (grow < M)
                    v = *reinterpret_cast<const float4*>(&X[grow * FIN + k0 + c4 * 4]);
                int k = k0 + c4 * 4;
                v.x = fmaxf(fmaf(v.x, ssc[k + 0], ssh[k + 0]), 0.f);
                v.y = fmaxf(fmaf(v.y, ssc[k + 1], ssh[k + 1]), 0.f);
                v.z = fmaxf(fmaf(v.z, ssc[k + 2], ssh[k + 2]), 0.f);
                v.w = fmaxf(fmaf(v.w, ssc[k + 3], ssh[k + 3]), 0.f);
                *reinterpret_cast<float4*>(&Xs[r][c4 * 4]) = v;
            }
        }
        __syncthreads();

#pragma unroll 4
        for (int kk = 0; kk < 64; ++kk) {
            float b0 = Ws[kk][tx];
            float b1 = (tx < 8) ? Ws[kk][32 + tx] : 0.f;
#pragma unroll
            for (int i = 0; i < 8; ++i) {
                float a = Xs[ty + 8 * i][kk];
                acc[i][0] = fmaf(a, b0, acc[i][0]);
                acc[i][1] = fmaf(a, b1, acc[i][1]);
            }
        }
        __syncthreads();
    }

#pragma unroll
    for (int i = 0; i < 8; ++i) {
        int grow = row0 + ty + 8 * i;
        if (grow < M) {
            out[grow * F + tx] = acc[i][0];
            if (tx < 8) out[grow * F + 32 + tx] = acc[i][1];
        }
    }
}

// ---------------- SpMM F=128 (fp16 gathers, fp32 accum) + fused BN stats ----------------
// int2 at h[col*32 + lane] holds halfs (features) 4*lane .. 4*lane+3.
__global__ __launch_bounds__(256) void spmm128_kernel(
    const int2* __restrict__ h,
    const float* __restrict__ bias,
    float* __restrict__ out, int layer, int M)
{
    __shared__ float bsum[128], bsq[128];
    const int warp = blockIdx.x * 8 + (threadIdx.x >> 5);
    const int lane = threadIdx.x & 31;
    const int tid = threadIdx.x;

    if (tid < 128) { bsum[tid] = 0.f; bsq[tid] = 0.f; }
    __syncthreads();

    float4 acc = make_float4(0.f, 0.f, 0.f, 0.f);
    if (warp < M) {
        const int s = d_rowptr[warp];
        const int e = d_rowptr[warp + 1];
        int base = s;
        for (; base + 32 <= e; base += 32) {
            int2 md = d_ecolw[base + lane];
            int colr = md.x;
            float wr = __int_as_float(md.y);
#pragma unroll
            for (int j = 0; j < 32; ++j) {
                int col = __shfl_sync(0xffffffffu, colr, j);
                float w = __shfl_sync(0xffffffffu, wr, j);
                int2 raw = __ldg(&h[col * 32 + lane]);
                float2 f0 = __half22float2(*reinterpret_cast<__half2*>(&raw.x));
                float2 f1 = __half22float2(*reinterpret_cast<__half2*>(&raw.y));
                acc.x = fmaf(w, f0.x, acc.x);
                acc.y = fmaf(w, f0.y, acc.y);
                acc.z = fmaf(w, f1.x, acc.z);
                acc.w = fmaf(w, f1.y, acc.w);
            }
        }
        if (base < e) {
            int n = e - base;
            int2 md = (lane < n) ? d_ecolw[base + lane] : make_int2(0, 0);
            int colr = md.x;
            float wr = __int_as_float(md.y);
            for (int j = 0; j < n; ++j) {
                int col = __shfl_sync(0xffffffffu, colr, j);
                float w = __shfl_sync(0xffffffffu, wr, j);
                int2 raw = __ldg(&h[col * 32 + lane]);
                float2 f0 = __half22float2(*reinterpret_cast<__half2*>(&raw.x));
                float2 f1 = __half22float2(*reinterpret_cast<__half2*>(&raw.y));
                acc.x = fmaf(w, f0.x, acc.x);
                acc.y = fmaf(w, f0.y, acc.y);
                acc.z = fmaf(w, f1.x, acc.z);
                acc.w = fmaf(w, f1.y, acc.w);
            }
        }
        // acc maps to features 4*lane .. 4*lane+3 (linear layout)
        const int f0i = lane * 4;
        float4 b = *reinterpret_cast<const float4*>(&bias[f0i]);
        acc.x += b.x; acc.y += b.y; acc.z += b.z; acc.w += b.w;
        *reinterpret_cast<float4*>(&out[warp * 128 + f0i]) = acc;

        atomicAdd(&bsum[f0i + 0], acc.x);
        atomicAdd(&bsum[f0i + 1], acc.y);
        atomicAdd(&bsum[f0i + 2], acc.z);
        atomicAdd(&bsum[f0i + 3], acc.w);
        atomicAdd(&bsq[f0i + 0], acc.x * acc.x);
        atomicAdd(&bsq[f0i + 1], acc.y * acc.y);
        atomicAdd(&bsq[f0i + 2], acc.z * acc.z);
        atomicAdd(&bsq[f0i + 3], acc.w * acc.w);
    }
    __syncthreads();
    if (tid < 128) {
        atomicAdd(&d_sum[layer][tid], bsum[tid]);
        atomicAdd(&d_sumsq[layer][tid], bsq[tid]);
    }
}

// ---------------- SpMM F=40 (fp32) ----------------
__global__ __launch_bounds__(256) void spmm40_kernel(
    const float* __restrict__ h, const float* __restrict__ bias,
    float* __restrict__ out, int M)
{
    const int warp = blockIdx.x * 8 + (threadIdx.x >> 5);
    const int lane = threadIdx.x & 31;
    if (warp >= M) return;
    const int s = d_rowptr[warp];
    const int e = d_rowptr[warp + 1];

    float acc0 = 0.f, acc1 = 0.f;
    int base = s;
    for (; base + 32 <= e; base += 32) {
        int2 md = d_ecolw[base + lane];
        int colr = md.x;
        float wr = __int_as_float(md.y);
#pragma unroll
        for (int j = 0; j < 32; ++j) {
            int col = __shfl_sync(0xffffffffu, colr, j);
            float w = __shfl_sync(0xffffffffu, wr, j);
            float v0 = __ldg(&h[col * FOUT + lane]);
            acc0 = fmaf(w, v0, acc0);
            if (lane < 8) {
                float v1 = __ldg(&h[col * FOUT + 32 + lane]);
                acc1 = fmaf(w, v1, acc1);
            }
        }
    }
    if (base < e) {
        int n = e - base;
        int2 md = (lane < n) ? d_ecolw[base + lane] : make_int2(0, 0);
        int colr = md.x;
        float wr = __int_as_float(md.y);
        for (int j = 0; j < n; ++j) {
            int col = __shfl_sync(0xffffffffu, colr, j);
            float w = __shfl_sync(0xffffffffu, wr, j);
            float v0 = __ldg(&h[col * FOUT + lane]);
            acc0 = fmaf(w, v0, acc0);
            if (lane < 8) {
                float v1 = __ldg(&h[col * FOUT + 32 + lane]);
                acc1 = fmaf(w, v1, acc1);
            }
        }
    }
    out[warp * FOUT + lane] = acc0 + bias[lane];
    if (lane < 8) out[warp * FOUT + 32 + lane] = acc1 + bias[32 + lane];
}

// ---------------- launch ----------------
extern "C" void kernel_launch(void* const* d_in, const int* in_sizes, int n_in,
                              void* d_out, int out_size)
{
    const float* x   = (const float*)d_in[0];
    const int*   er  = (const int*)d_in[1];
    const int*   ec  = (const int*)d_in[2];
    const float* ew  = (const float*)d_in[3];
    const float* W0  = (const float*)d_in[4];
    const float* b0  = (const float*)d_in[5];
    const float* g0  = (const float*)d_in[6];
    const float* be0 = (const float*)d_in[7];
    const float* W1  = (const float*)d_in[8];
    const float* b1  = (const float*)d_in[9];
    const float* g1  = (const float*)d_in[10];
    const float* be1 = (const float*)d_in[11];
    const float* W2  = (const float*)d_in[12];
    const float* b2  = (const float*)d_in[13];
    float* out = (float*)d_out;

    const int M = in_sizes[0] / FIN;
    const int E = in_sizes[1];

    int2*  t0h; cudaGetSymbolAddress((void**)&t0h, d_t0h);
    float* t1;  cudaGetSymbolAddress((void**)&t1, d_t1);
    float* t2;  cudaGetSymbolAddress((void**)&t2, d_t2);

    // CSR build
    zero_kernel<<<(NN + 255) / 256, 256>>>();
    const int E8 = (E + 7) / 8;
    hist_kernel<<<(E8 + 255) / 256, 256>>>(er, E);
    scan_kernel<<<1, 1024>>>(M);
    scatter_kernel<<<(E8 + 255) / 256, 256>>>(er, ec, ew, E);

    const int g128 = (M + 127) / 128;
    const int gsp  = (M + 7) / 8;

    // layer 0
    gemm128_kernel<false><<<g128, 256>>>(x, W0, (__half2*)t0h, nullptr, nullptr, 0, M);
    spmm128_kernel<<<gsp, 256>>>(t0h, b0, t1, 0, M);

    // layer 1 (BN finalize of layer-0 stats fused into gemm prologue)
    gemm128_kernel<true><<<g128, 256>>>(t1, W1, (__half2*)t0h, g0, be0, 0, M);
    spmm128_kernel<<<gsp, 256>>>(t0h, b1, t1, 1, M);

    // layer 2 (BN finalize of layer-1 stats fused into gemm40 prologue)
    gemm40_kernel<<<(M + 63) / 64, dim3(32, 8)>>>(t1, W2, t2, g1, be1, 1, M);
    spmm40_kernel<<<gsp, 256>>>(t2, b2, out, M);
}

// round 12
// speedup vs baseline: 1.7708x; 1.0974x over previous
#include <cuda_runtime.h>
#include <cuda_bf16.h>
#include <cuda_fp16.h>
#include <cstdint>

#define NN 50000
#define FIN 128
#define FOUT 40
#define EMAX 1600000
#define BN_EPS 1e-5f

// ---------------- device scratch ----------------
__device__ int2   d_t0h[NN * 32];           // fp16 gemm output (128 halfs = 32 int2 per row)
__device__ float  d_t1[NN * FIN];           // spmm output (fp32 activations)
__device__ __half d_t2h[NN * FOUT + 64];    // fp16 layer-2 gemm output
__device__ int2   d_ecolw[EMAX];
__device__ int    d_epos[EMAX];
__device__ int    d_counts[NN];
__device__ int    d_rowptr[NN + 1];
__device__ float  d_sum[2][FIN];
__device__ float  d_sumsq[2][FIN];

// ---------------- CSR build ----------------
__global__ void zero_kernel() {
    int i = blockIdx.x * blockDim.x + threadIdx.x;
    if (i < NN) d_counts[i] = 0;
    if (i < FIN) {
        d_sum[0][i] = 0.f; d_sum[1][i] = 0.f;
        d_sumsq[0][i] = 0.f; d_sumsq[1][i] = 0.f;
    }
}

__global__ void hist_kernel(const int* __restrict__ er, int E) {
    int i = blockIdx.x * blockDim.x + threadIdx.x;
    int e = i * 4;
    if (e + 4 <= E) {
        int4 r = *reinterpret_cast<const int4*>(&er[e]);
        int4 p;
        p.x = atomicAdd(&d_counts[r.x], 1);
        p.y = atomicAdd(&d_counts[r.y], 1);
        p.z = atomicAdd(&d_counts[r.z], 1);
        p.w = atomicAdd(&d_counts[r.w], 1);
        *reinterpret_cast<int4*>(&d_epos[e]) = p;
    } else {
        for (; e < E; ++e) d_epos[e] = atomicAdd(&d_counts[er[e]], 1);
    }
}

__global__ void scan_kernel(int Nn) {
    __shared__ int ssum[1024];
    int t = threadIdx.x;
    int chunk = (Nn + 1023) >> 10;
    int base = t * chunk;
    int s = 0;
    for (int i = 0; i < chunk; ++i) {
        int idx = base + i;
        if (idx < Nn) s += d_counts[idx];
    }
    ssum[t] = s;
    __syncthreads();
    for (int off = 1; off < 1024; off <<= 1) {
        int v = (t >= off) ? ssum[t - off] : 0;
        __syncthreads();
        ssum[t] += v;
        __syncthreads();
    }
    int run = (t > 0) ? ssum[t - 1] : 0;
    for (int i = 0; i < chunk; ++i) {
        int idx = base + i;
        if (idx < Nn) {
            d_rowptr[idx] = run;
            run += d_counts[idx];
        }
    }
    if (t == 1023) d_rowptr[Nn] = run;
}

__global__ void scatter_kernel(const int* __restrict__ er, const int* __restrict__ ec,
                               const float* __restrict__ ew, int E) {
    int i = blockIdx.x * blockDim.x + threadIdx.x;
    int e = i * 4;
    if (e + 4 <= E) {
        int4 r = *reinterpret_cast<const int4*>(&er[e]);
        int4 c = *reinterpret_cast<const int4*>(&ec[e]);
        float4 w = *reinterpret_cast<const float4*>(&ew[e]);
        int4 p = *reinterpret_cast<const int4*>(&d_epos[e]);
        d_ecolw[d_rowptr[r.x] + p.x] = make_int2(c.x, __float_as_int(w.x));
        d_ecolw[d_rowptr[r.y] + p.y] = make_int2(c.y, __float_as_int(w.y));
        d_ecolw[d_rowptr[r.z] + p.z] = make_int2(c.z, __float_as_int(w.z));
        d_ecolw[d_rowptr[r.w] + p.w] = make_int2(c.w, __float_as_int(w.w));
    } else {
        for (; e < E; ++e) {
            int pos = d_rowptr[er[e]] + d_epos[e];
            d_ecolw[pos] = make_int2(ec[e], __float_as_int(ew[e]));
        }
    }
}

// ---------------- 3xTF32 helpers ----------------
__device__ __forceinline__ void tf32_split(float a, uint32_t& hi, uint32_t& lo) {
    asm("cvt.rna.tf32.f32 %0, %1;" : "=r"(hi) : "f"(a));
    float r = a - __uint_as_float(hi);
    asm("cvt.rna.tf32.f32 %0, %1;" : "=r"(lo) : "f"(r));
}

__device__ __forceinline__ void mma_tf32(float* c, const uint32_t* a, uint32_t b0, uint32_t b1) {
    asm volatile("mma.sync.aligned.m16n8k8.row.col.f32.tf32.tf32.f32 "
        "{%0,%1,%2,%3}, {%4,%5,%6,%7}, {%8,%9}, {%0,%1,%2,%3};"
        : "+f"(c[0]), "+f"(c[1]), "+f"(c[2]), "+f"(c[3])
        : "r"(a[0]), "r"(a[1]), "r"(a[2]), "r"(a[3]), "r"(b0), "r"(b1));
}

// ---------------- GEMM 128x128 via 3xTF32, pre-split operands, fp16 output ----------------
template <bool BN>
__global__ __launch_bounds__(256) void gemm128_kernel(
    const float* __restrict__ X, const float* __restrict__ W,
    __half2* __restrict__ outh,
    const float* __restrict__ g, const float* __restrict__ be,
    int layer, int M)
{
    __shared__ uint32_t Xhi[128][36], Xlo[128][36];
    __shared__ uint32_t Whi[32][136], Wlo[32][136];
    __shared__ float ssc[128], ssh[128];

    const int tid = threadIdx.x;
    const int lane = tid & 31;
    const int warp = tid >> 5;
    const int gid = lane >> 2;
    const int tig = lane & 3;
    const int wm = warp >> 1;
    const int wn = warp & 1;
    const int row0 = blockIdx.x * 128;

    if (BN) {
        if (tid < 128) {
            const float invN = 1.f / (float)NN;
            float mean = d_sum[layer][tid] * invN;
            float var = d_sumsq[layer][tid] * invN - mean * mean;
            float sc = g[tid] * rsqrtf(var + BN_EPS);
            ssc[tid] = sc;
            ssh[tid] = fmaf(-mean, sc, be[tid]);
        }
        __syncthreads();
    }

    float c[2][8][4];
#pragma unroll
    for (int mt = 0; mt < 2; ++mt)
#pragma unroll
        for (int nt = 0; nt < 8; ++nt)
#pragma unroll
            for (int q = 0; q < 4; ++q) c[mt][nt][q] = 0.f;

    for (int kt = 0; kt < 4; ++kt) {
        const int k0 = kt * 32;
#pragma unroll
        for (int l = 0; l < 4; ++l) {
            int idx = tid + 256 * l;
            int kk = idx >> 5;
            int c4 = idx & 31;
            float4 v = *reinterpret_cast<const float4*>(&W[(k0 + kk) * 128 + c4 * 4]);
            uint4 h, lo;
            tf32_split(v.x, h.x, lo.x);
            tf32_split(v.y, h.y, lo.y);
            tf32_split(v.z, h.z, lo.z);
            tf32_split(v.w, h.w, lo.w);
            *reinterpret_cast<uint4*>(&Whi[kk][c4 * 4]) = h;
            *reinterpret_cast<uint4*>(&Wlo[kk][c4 * 4]) = lo;
        }
#pragma unroll
        for (int l = 0; l < 4; ++l) {
            int idx = tid + 256 * l;
            int r = idx >> 3;
            int c4 = idx & 7;
            int grow = row0 + r;
            float4 v = make_float4(0.f, 0.f, 0.f, 0.f);
            if (grow < M)
                v = *reinterpret_cast<const float4*>(&X[grow * 128 + k0 + c4 * 4]);
            if (BN) {
                int k = k0 + c4 * 4;
                v.x = fmaxf(fmaf(v.x, ssc[k + 0], ssh[k + 0]), 0.f);
                v.y = fmaxf(fmaf(v.y, ssc[k + 1], ssh[k + 1]), 0.f);
                v.z = fmaxf(fmaf(v.z, ssc[k + 2], ssh[k + 2]), 0.f);
                v.w = fmaxf(fmaf(v.w, ssc[k + 3], ssh[k + 3]), 0.f);
            }
            uint4 h, lo;
            tf32_split(v.x, h.x, lo.x);
            tf32_split(v.y, h.y, lo.y);
            tf32_split(v.z, h.z, lo.z);
            tf32_split(v.w, h.w, lo.w);
            *reinterpret_cast<uint4*>(&Xhi[r][c4 * 4]) = h;
            *reinterpret_cast<uint4*>(&Xlo[r][c4 * 4]) = lo;
        }
        __syncthreads();

#pragma unroll
        for (int ks = 0; ks < 32; ks += 8) {
            uint32_t ahi[2][4], alo[2][4];
#pragma unroll
            for (int mt = 0; mt < 2; ++mt) {
                int rb = wm * 32 + mt * 16;
                ahi[mt][0] = Xhi[rb + gid][ks + tig];
                ahi[mt][1] = Xhi[rb + gid + 8][ks + tig];
                ahi[mt][2] = Xhi[rb + gid][ks + tig + 4];
                ahi[mt][3] = Xhi[rb + gid + 8][ks + tig + 4];
                alo[mt][0] = Xlo[rb + gid][ks + tig];
                alo[mt][1] = Xlo[rb + gid + 8][ks + tig];
                alo[mt][2] = Xlo[rb + gid][ks + tig + 4];
                alo[mt][3] = Xlo[rb + gid + 8][ks + tig + 4];
            }
#pragma unroll
            for (int nt = 0; nt < 8; ++nt) {
                int ncol = wn * 64 + nt * 8 + gid;
                uint32_t bh0 = Whi[ks + tig][ncol];
                uint32_t bh1 = Whi[ks + tig + 4][ncol];
                uint32_t bl0 = Wlo[ks + tig][ncol];
                uint32_t bl1 = Wlo[ks + tig + 4][ncol];
#pragma unroll
                for (int mt = 0; mt < 2; ++mt) {
                    mma_tf32(c[mt][nt], ahi[mt], bh0, bh1);
                    mma_tf32(c[mt][nt], alo[mt], bh0, bh1);
                    mma_tf32(c[mt][nt], ahi[mt], bl0, bl1);
                }
            }
        }
        __syncthreads();
    }

    // fp16 epilogue: half index == feature index (linear row layout)
#pragma unroll
    for (int mt = 0; mt < 2; ++mt) {
#pragma unroll
        for (int nt = 0; nt < 8; ++nt) {
            int col = wn * 64 + nt * 8 + 2 * tig;
            int r0 = row0 + wm * 32 + mt * 16 + gid;
            if (r0 < M)
                outh[r0 * 64 + (col >> 1)] =
                    __float22half2_rn(make_float2(c[mt][nt][0], c[mt][nt][1]));
            if (r0 + 8 < M)
                outh[(r0 + 8) * 64 + (col >> 1)] =
                    __float22half2_rn(make_float2(c[mt][nt][2], c[mt][nt][3]));
        }
    }
}

// ---------------- GEMM F=40 (final layer, fp32 compute, fp16 output) ----------------
__global__ __launch_bounds__(256) void gemm40_kernel(
    const float* __restrict__ X, const float* __restrict__ W,
    __half* __restrict__ outh,
    const float* __restrict__ g, const float* __restrict__ be,
    int layer, int M)
{
    constexpr int F = FOUT;
    __shared__ float Xs[64][64];
    __shared__ float Ws[64][F];
    __shared__ float ssc[128], ssh[128];

    const int tx = threadIdx.x;
    const int ty = threadIdx.y;
    const int tid = ty * 32 + tx;
    const int row0 = blockIdx.x * 64;

    if (tid < 128) {
        const float invN = 1.f / (float)NN;
        float mean = d_sum[layer][tid] * invN;
        float var = d_sumsq[layer][tid] * invN - mean * mean;
        float sc = g[tid] * rsqrtf(var + BN_EPS);
        ssc[tid] = sc;
        ssh[tid] = fmaf(-mean, sc, be[tid]);
    }
    __syncthreads();

    float acc[8][2];
#pragma unroll
    for (int i = 0; i < 8; ++i) { acc[i][0] = 0.f; acc[i][1] = 0.f; }

    for (int kt = 0; kt < 2; ++kt) {
        const int k0 = kt * 64;
        {
            const int nv4 = 64 * F / 4;
            for (int idx = tid; idx < nv4; idx += 256) {
                int r = idx / (F / 4);
                int c4 = idx % (F / 4);
                float4 v = *reinterpret_cast<const float4*>(&W[(k0 + r) * F + c4 * 4]);
                *reinterpret_cast<float4*>(&Ws[r][c4 * 4]) = v;
            }
        }
        {
#pragma unroll
            for (int l = 0; l < 4; ++l) {
                int idx = tid + 256 * l;
                int r = idx >> 4;
                int c4 = idx & 15;
                int grow = row0 + r;
                float4 v = make_float4(0.f, 0.f, 0.f, 0.f);
                if (grow < M)
                    v = *reinterpret_cast<const float4*>(&X[grow * FIN + k0 + c4 * 4]);
                int k = k0 + c4 * 4;
                v.x = fmaxf(fmaf(v.x, ssc[k + 0], ssh[k + 0]), 0.f);
                v.y = fmaxf(fmaf(v.y, ssc[k + 1], ssh[k + 1]), 0.f);
                v.z = fmaxf(fmaf(v.z, ssc[k + 2], ssh[k + 2]), 0.f);
                v.w = fmaxf(fmaf(v.w, ssc[k + 3], ssh[k + 3]), 0.f);
                *reinterpret_cast<float4*>(&Xs[r][c4 * 4]) = v;
            }
        }
        __syncthreads();

#pragma unroll 4
        for (int kk = 0; kk < 64; ++kk) {
            float b0 = Ws[kk][tx];
            float b1 = (tx < 8) ? Ws[kk][32 + tx] : 0.f;
#pragma unroll
            for (int i = 0; i < 8; ++i) {
                float a = Xs[ty + 8 * i][kk];
                acc[i][0] = fmaf(a, b0, acc[i][0]);
                acc[i][1] = fmaf(a, b1, acc[i][1]);
            }
        }
        __syncthreads();
    }

#pragma unroll
    for (int i = 0; i < 8; ++i) {
        int grow = row0 + ty + 8 * i;
        if (grow < M) {
            outh[grow * F + tx] = __float2half_rn(acc[i][0]);
            if (tx < 8) outh[grow * F + 32 + tx] = __float2half_rn(acc[i][1]);
        }
    }
}

// ---------------- SpMM F=128 (fp16 gathers) + BN stats via smem tree-reduce ----------------
// int2 at h[col*32 + lane] holds halfs (features) 4*lane .. 4*lane+3.
__global__ __launch_bounds__(256) void spmm128_kernel(
    const int2* __restrict__ h,
    const float* __restrict__ bias,
    float* __restrict__ out, int layer, int M)
{
    __shared__ float sacc[8][128];
    const int warp = blockIdx.x * 8 + (threadIdx.x >> 5);
    const int wid = threadIdx.x >> 5;
    const int lane = threadIdx.x & 31;
    const int tid = threadIdx.x;

    float4 acc = make_float4(0.f, 0.f, 0.f, 0.f);
    if (warp < M) {
        const int s = d_rowptr[warp];
        const int e = d_rowptr[warp + 1];
        int base = s;
        for (; base + 32 <= e; base += 32) {
            int2 md = d_ecolw[base + lane];
            int colr = md.x;
            float wr = __int_as_float(md.y);
#pragma unroll
            for (int j = 0; j < 32; ++j) {
                int col = __shfl_sync(0xffffffffu, colr, j);
                float w = __shfl_sync(0xffffffffu, wr, j);
                int2 raw = __ldg(&h[col * 32 + lane]);
                float2 f0 = __half22float2(*reinterpret_cast<__half2*>(&raw.x));
                float2 f1 = __half22float2(*reinterpret_cast<__half2*>(&raw.y));
                acc.x = fmaf(w, f0.x, acc.x);
                acc.y = fmaf(w, f0.y, acc.y);
                acc.z = fmaf(w, f1.x, acc.z);
                acc.w = fmaf(w, f1.y, acc.w);
            }
        }
        if (base < e) {
            int n = e - base;
            int2 md = (lane < n) ? d_ecolw[base + lane] : make_int2(0, 0);
            int colr = md.x;
            float wr = __int_as_float(md.y);
            for (int j = 0; j < n; ++j) {
                int col = __shfl_sync(0xffffffffu, colr, j);
                float w = __shfl_sync(0xffffffffu, wr, j);
                int2 raw = __ldg(&h[col * 32 + lane]);
                float2 f0 = __half22float2(*reinterpret_cast<__half2*>(&raw.x));
                float2 f1 = __half22float2(*reinterpret_cast<__half2*>(&raw.y));
                acc.x = fmaf(w, f0.x, acc.x);
                acc.y = fmaf(w, f0.y, acc.y);
                acc.z = fmaf(w, f1.x, acc.z);
                acc.w = fmaf(w, f1.y, acc.w);
            }
        }
        const int f0i = lane * 4;
        float4 b = *reinterpret_cast<const float4*>(&bias[f0i]);
        acc.x += b.x; acc.y += b.y; acc.z += b.z; acc.w += b.w;
        *reinterpret_cast<float4*>(&out[warp * 128 + f0i]) = acc;
    }
    // stats: store (zeros for inactive rows), then tree-reduce, 2 global atomics per feature
    *reinterpret_cast<float4*>(&sacc[wid][lane * 4]) = acc;
    __syncthreads();
    if (tid < 128) {
        float s = 0.f, s2 = 0.f;
#pragma unroll
        for (int w = 0; w < 8; ++w) {
            float v = sacc[w][tid];
            s += v;
            s2 = fmaf(v, v, s2);
        }
        atomicAdd(&d_sum[layer][tid], s);
        atomicAdd(&d_sumsq[layer][tid], s2);
    }
}

// ---------------- SpMM F=40 (fp16 gathers, fp32 accum & output) ----------------
// row = 40 halfs = 20 half2; lane l<20 covers features 2l, 2l+1.
__global__ __launch_bounds__(256) void spmm40_kernel(
    const __half2* __restrict__ h,
    const float* __restrict__ bias,
    float* __restrict__ out, int M)
{
    const int warp = blockIdx.x * 8 + (threadIdx.x >> 5);
    const int lane = threadIdx.x & 31;
    if (warp >= M) return;
    const int s = d_rowptr[warp];
    const int e = d_rowptr[warp + 1];

    float2 acc = make_float2(0.f, 0.f);
    int base = s;
    for (; base + 32 <= e; base += 32) {
        int2 md = d_ecolw[base + lane];
        int colr = md.x;
        float wr = __int_as_float(md.y);
#pragma unroll
        for (int j = 0; j < 32; ++j) {
            int col = __shfl_sync(0xffffffffu, colr, j);
            float w = __shfl_sync(0xffffffffu, wr, j);
            if (lane < 20) {
                float2 v = __half22float2(__ldg(&h[col * 20 + lane]));
                acc.x = fmaf(w, v.x, acc.x);
                acc.y = fmaf(w, v.y, acc.y);
            }
        }
    }
    if (base < e) {
        int n = e - base;
        int2 md = (lane < n) ? d_ecolw[base + lane] : make_int2(0, 0);
        int colr = md.x;
        float wr = __int_as_float(md.y);
        for (int j = 0; j < n; ++j) {
            int col = __shfl_sync(0xffffffffu, colr, j);
            float w = __shfl_sync(0xffffffffu, wr, j);
            if (lane < 20) {
                float2 v = __half22float2(__ldg(&h[col * 20 + lane]));
                acc.x = fmaf(w, v.x, acc.x);
                acc.y = fmaf(w, v.y, acc.y);
            }
        }
    }
    if (lane < 20) {
        acc.x += bias[2 * lane];
        acc.y += bias[2 * lane + 1];
        *reinterpret_cast<float2*>(&out[warp * FOUT + 2 * lane]) = acc;
    }
}

// ---------------- launch ----------------
extern "C" void kernel_launch(void* const* d_in, const int* in_sizes, int n_in,
                              void* d_out, int out_size)
{
    const float* x   = (const float*)d_in[0];
    const int*   er  = (const int*)d_in[1];
    const int*   ec  = (const int*)d_in[2];
    const float* ew  = (const float*)d_in[3];
    const float* W0  = (const float*)d_in[4];
    const float* b0  = (const float*)d_in[5];
    const float* g0  = (const float*)d_in[6];
    const float* be0 = (const float*)d_in[7];
    const float* W1  = (const float*)d_in[8];
    const float* b1  = (const float*)d_in[9];
    const float* g1  = (const float*)d_in[10];
    const float* be1 = (const float*)d_in[11];
    const float* W2  = (const float*)d_in[12];
    const float* b2  = (const float*)d_in[13];
    float* out = (float*)d_out;

    const int M = in_sizes[0] / FIN;
    const int E = in_sizes[1];

    int2*   t0h; cudaGetSymbolAddress((void**)&t0h, d_t0h);
    float*  t1;  cudaGetSymbolAddress((void**)&t1, d_t1);
    __half* t2h; cudaGetSymbolAddress((void**)&t2h, d_t2h);

    // CSR build
    zero_kernel<<<(NN + 255) / 256, 256>>>();
    const int E4 = (E + 3) / 4;
    hist_kernel<<<(E4 + 255) / 256, 256>>>(er, E);
    scan_kernel<<<1, 1024>>>(M);
    scatter_kernel<<<(E4 + 255) / 256, 256>>>(er, ec, ew, E);

    const int g128 = (M + 127) / 128;
    const int gsp  = (M + 7) / 8;

    // layer 0
    gemm128_kernel<false><<<g128, 256>>>(x, W0, (__half2*)t0h, nullptr, nullptr, 0, M);
    spmm128_kernel<<<gsp, 256>>>(t0h, b0, t1, 0, M);

    // layer 1 (BN finalize of layer-0 stats fused into gemm prologue)
    gemm128_kernel<true><<<g128, 256>>>(t1, W1, (__half2*)t0h, g0, be0, 0, M);
    spmm128_kernel<<<gsp, 256>>>(t0h, b1, t1, 1, M);

    // layer 2 (BN finalize of layer-1 stats fused into gemm40 prologue)
    gemm40_kernel<<<(M + 63) / 64, dim3(32, 8)>>>(t1, W2, t2h, g1, be1, 1, M);
    spmm40_kernel<<<gsp, 256>>>((const __half2*)t2h, b2, out, M);
}

// round 13
// speedup vs baseline: 1.9326x; 1.0914x over previous
#include <cuda_runtime.h>
#include <cuda_bf16.h>
#include <cuda_fp16.h>
#include <cstdint>

#define NN 50000
#define FIN 128
#define FOUT 40
#define EMAX 1600000
#define BN_EPS 1e-5f

// ---------------- device scratch ----------------
__device__ int2   d_t0h[NN * 32];           // fp16 gemm output (128 halfs = 32 int2 per row)
__device__ int2   d_t1h[NN * 32];           // fp16 spmm output (activations)
__device__ __half d_t2h[NN * FOUT + 64];    // fp16 layer-2 gemm output
__device__ int2   d_ecolw[EMAX];
__device__ int    d_epos[EMAX];
__device__ int    d_counts[NN];
__device__ int    d_rowptr[NN + 1];
__device__ float  d_sum[2][FIN];
__device__ float  d_sumsq[2][FIN];

// ---------------- CSR build pieces ----------------
__global__ void zero_kernel() {
    int i = blockIdx.x * blockDim.x + threadIdx.x;
    if (i < NN) d_counts[i] = 0;
    if (i < FIN) {
        d_sum[0][i] = 0.f; d_sum[1][i] = 0.f;
        d_sumsq[0][i] = 0.f; d_sumsq[1][i] = 0.f;
    }
}

__device__ __forceinline__ void hist_body(const int* __restrict__ er, int E, int bid) {
    int i = bid * 256 + threadIdx.x;
    int e = i * 4;
    if (e + 4 <= E) {
        int4 r = *reinterpret_cast<const int4*>(&er[e]);
        int4 p;
        p.x = atomicAdd(&d_counts[r.x], 1);
        p.y = atomicAdd(&d_counts[r.y], 1);
        p.z = atomicAdd(&d_counts[r.z], 1);
        p.w = atomicAdd(&d_counts[r.w], 1);
        *reinterpret_cast<int4*>(&d_epos[e]) = p;
    } else {
        for (; e < E; ++e) d_epos[e] = atomicAdd(&d_counts[er[e]], 1);
    }
}

__global__ void scan_kernel(int Nn) {
    __shared__ int ssum[1024];
    int t = threadIdx.x;
    int chunk = (Nn + 1023) >> 10;
    int base = t * chunk;
    int s = 0;
    for (int i = 0; i < chunk; ++i) {
        int idx = base + i;
        if (idx < Nn) s += d_counts[idx];
    }
    ssum[t] = s;
    __syncthreads();
    for (int off = 1; off < 1024; off <<= 1) {
        int v = (t >= off) ? ssum[t - off] : 0;
        __syncthreads();
        ssum[t] += v;
        __syncthreads();
    }
    int run = (t > 0) ? ssum[t - 1] : 0;
    for (int i = 0; i < chunk; ++i) {
        int idx = base + i;
        if (idx < Nn) {
            d_rowptr[idx] = run;
            run += d_counts[idx];
        }
    }
    if (t == 1023) d_rowptr[Nn] = run;
}

__global__ void scatter_kernel(const int* __restrict__ er, const int* __restrict__ ec,
                               const float* __restrict__ ew, int E) {
    int i = blockIdx.x * blockDim.x + threadIdx.x;
    int e = i * 4;
    if (e + 4 <= E) {
        int4 r = *reinterpret_cast<const int4*>(&er[e]);
        int4 c = *reinterpret_cast<const int4*>(&ec[e]);
        float4 w = *reinterpret_cast<const float4*>(&ew[e]);
        int4 p = *reinterpret_cast<const int4*>(&d_epos[e]);
        d_ecolw[d_rowptr[r.x] + p.x] = make_int2(c.x, __float_as_int(w.x));
        d_ecolw[d_rowptr[r.y] + p.y] = make_int2(c.y, __float_as_int(w.y));
        d_ecolw[d_rowptr[r.z] + p.z] = make_int2(c.z, __float_as_int(w.z));
        d_ecolw[d_rowptr[r.w] + p.w] = make_int2(c.w, __float_as_int(w.w));
    } else {
        for (; e < E; ++e) {
            int pos = d_rowptr[er[e]] + d_epos[e];
            d_ecolw[pos] = make_int2(ec[e], __float_as_int(ew[e]));
        }
    }
}

// ---------------- 3xTF32 helpers ----------------
__device__ __forceinline__ void tf32_split(float a, uint32_t& hi, uint32_t& lo) {
    asm("cvt.rna.tf32.f32 %0, %1;" : "=r"(hi) : "f"(a));
    float r = a - __uint_as_float(hi);
    asm("cvt.rna.tf32.f32 %0, %1;" : "=r"(lo) : "f"(r));
}

__device__ __forceinline__ void mma_tf32(float* c, const uint32_t* a, uint32_t b0, uint32_t b1) {
    asm volatile("mma.sync.aligned.m16n8k8.row.col.f32.tf32.tf32.f32 "
        "{%0,%1,%2,%3}, {%4,%5,%6,%7}, {%8,%9}, {%0,%1,%2,%3};"
        : "+f"(c[0]), "+f"(c[1]), "+f"(c[2]), "+f"(c[3])
        : "r"(a[0]), "r"(a[1]), "r"(a[2]), "r"(a[3]), "r"(b0), "r"(b1));
}

// ---------------- GEMM 128x128 body (3xTF32, pre-split, fp16 I/O options) ----------------
// XH: X is fp16 (int2-packed, 32 int2 per row); else fp32.
template <bool BN, bool XH>
__device__ __forceinline__ void gemm128_body(
    const void* __restrict__ Xv, const float* __restrict__ W,
    __half2* __restrict__ outh,
    const float* __restrict__ g, const float* __restrict__ be,
    int layer, int M, int bid)
{
    __shared__ uint32_t Xhi[128][36], Xlo[128][36];
    __shared__ uint32_t Whi[32][136], Wlo[32][136];
    __shared__ float ssc[128], ssh[128];

    const float* __restrict__ Xf = (const float*)Xv;
    const int2* __restrict__ Xh = (const int2*)Xv;

    const int tid = threadIdx.x;
    const int lane = tid & 31;
    const int warp = tid >> 5;
    const int gid = lane >> 2;
    const int tig = lane & 3;
    const int wm = warp >> 1;
    const int wn = warp & 1;
    const int row0 = bid * 128;

    if (BN) {
        if (tid < 128) {
            const float invN = 1.f / (float)NN;
            float mean = d_sum[layer][tid] * invN;
            float var = d_sumsq[layer][tid] * invN - mean * mean;
            float sc = g[tid] * rsqrtf(var + BN_EPS);
            ssc[tid] = sc;
            ssh[tid] = fmaf(-mean, sc, be[tid]);
        }
        __syncthreads();
    }

    float c[2][8][4];
#pragma unroll
    for (int mt = 0; mt < 2; ++mt)
#pragma unroll
        for (int nt = 0; nt < 8; ++nt)
#pragma unroll
            for (int q = 0; q < 4; ++q) c[mt][nt][q] = 0.f;

    for (int kt = 0; kt < 4; ++kt) {
        const int k0 = kt * 32;
#pragma unroll
        for (int l = 0; l < 4; ++l) {
            int idx = tid + 256 * l;
            int kk = idx >> 5;
            int c4 = idx & 31;
            float4 v = *reinterpret_cast<const float4*>(&W[(k0 + kk) * 128 + c4 * 4]);
            uint4 h, lo;
            tf32_split(v.x, h.x, lo.x);
            tf32_split(v.y, h.y, lo.y);
            tf32_split(v.z, h.z, lo.z);
            tf32_split(v.w, h.w, lo.w);
            *reinterpret_cast<uint4*>(&Whi[kk][c4 * 4]) = h;
            *reinterpret_cast<uint4*>(&Wlo[kk][c4 * 4]) = lo;
        }
#pragma unroll
        for (int l = 0; l < 4; ++l) {
            int idx = tid + 256 * l;
            int r = idx >> 3;
            int c4 = idx & 7;
            int grow = row0 + r;
            float4 v = make_float4(0.f, 0.f, 0.f, 0.f);
            if (grow < M) {
                if (XH) {
                    int2 raw = __ldg(&Xh[grow * 32 + (k0 >> 2) + c4]);
                    float2 f0 = __half22float2(*reinterpret_cast<__half2*>(&raw.x));
                    float2 f1 = __half22float2(*reinterpret_cast<__half2*>(&raw.y));
                    v = make_float4(f0.x, f0.y, f1.x, f1.y);
                } else {
                    v = *reinterpret_cast<const float4*>(&Xf[grow * 128 + k0 + c4 * 4]);
                }
            }
            if (BN) {
                int k = k0 + c4 * 4;
                v.x = fmaxf(fmaf(v.x, ssc[k + 0], ssh[k + 0]), 0.f);
                v.y = fmaxf(fmaf(v.y, ssc[k + 1], ssh[k + 1]), 0.f);
                v.z = fmaxf(fmaf(v.z, ssc[k + 2], ssh[k + 2]), 0.f);
                v.w = fmaxf(fmaf(v.w, ssc[k + 3], ssh[k + 3]), 0.f);
            }
            uint4 h, lo;
            tf32_split(v.x, h.x, lo.x);
            tf32_split(v.y, h.y, lo.y);
            tf32_split(v.z, h.z, lo.z);
            tf32_split(v.w, h.w, lo.w);
            *reinterpret_cast<uint4*>(&Xhi[r][c4 * 4]) = h;
            *reinterpret_cast<uint4*>(&Xlo[r][c4 * 4]) = lo;
        }
        __syncthreads();

#pragma unroll
        for (int ks = 0; ks < 32; ks += 8) {
            uint32_t ahi[2][4], alo[2][4];
#pragma unroll
            for (int mt = 0; mt < 2; ++mt) {
                int rb = wm * 32 + mt * 16;
                ahi[mt][0] = Xhi[rb + gid][ks + tig];
                ahi[mt][1] = Xhi[rb + gid + 8][ks + tig];
                ahi[mt][2] = Xhi[rb + gid][ks + tig + 4];
                ahi[mt][3] = Xhi[rb + gid + 8][ks + tig + 4];
                alo[mt][0] = Xlo[rb + gid][ks + tig];
                alo[mt][1] = Xlo[rb + gid + 8][ks + tig];
                alo[mt][2] = Xlo[rb + gid][ks + tig + 4];
                alo[mt][3] = Xlo[rb + gid + 8][ks + tig + 4];
            }
#pragma unroll
            for (int nt = 0; nt < 8; ++nt) {
                int ncol = wn * 64 + nt * 8 + gid;
                uint32_t bh0 = Whi[ks + tig][ncol];
                uint32_t bh1 = Whi[ks + tig + 4][ncol];
                uint32_t bl0 = Wlo[ks + tig][ncol];
                uint32_t bl1 = Wlo[ks + tig + 4][ncol];
#pragma unroll
                for (int mt = 0; mt < 2; ++mt) {
                    mma_tf32(c[mt][nt], ahi[mt], bh0, bh1);
                    mma_tf32(c[mt][nt], alo[mt], bh0, bh1);
                    mma_tf32(c[mt][nt], ahi[mt], bl0, bl1);
                }
            }
        }
        __syncthreads();
    }

    // fp16 epilogue: half index == feature index (linear row layout)
#pragma unroll
    for (int mt = 0; mt < 2; ++mt) {
#pragma unroll
        for (int nt = 0; nt < 8; ++nt) {
            int col = wn * 64 + nt * 8 + 2 * tig;
            int r0 = row0 + wm * 32 + mt * 16 + gid;
            if (r0 < M)
                outh[r0 * 64 + (col >> 1)] =
                    __float22half2_rn(make_float2(c[mt][nt][0], c[mt][nt][1]));
            if (r0 + 8 < M)
                outh[(r0 + 8) * 64 + (col >> 1)] =
                    __float22half2_rn(make_float2(c[mt][nt][2], c[mt][nt][3]));
        }
    }
}

// fused front: blocks [0,gB) run gemm128 layer-0, the rest run hist
__global__ __launch_bounds__(256) void fused0_kernel(
    const float* __restrict__ x, const float* __restrict__ W0,
    __half2* __restrict__ outh, const int* __restrict__ er,
    int E, int M, int gB)
{
    if ((int)blockIdx.x < gB)
        gemm128_body<false, false>(x, W0, outh, nullptr, nullptr, 0, M, blockIdx.x);
    else
        hist_body(er, E, blockIdx.x - gB);
}

__global__ __launch_bounds__(256) void gemm128h_kernel(
    const int2* __restrict__ X, const float* __restrict__ W,
    __half2* __restrict__ outh,
    const float* __restrict__ g, const float* __restrict__ be,
    int layer, int M)
{
    gemm128_body<true, true>(X, W, outh, g, be, layer, M, blockIdx.x);
}

// ---------------- GEMM F=40 (fp16 in, fp32 compute, fp16 out, BN fused) ----------------
__global__ __launch_bounds__(256) void gemm40_kernel(
    const int2* __restrict__ Xh, const float* __restrict__ W,
    __half* __restrict__ outh,
    const float* __restrict__ g, const float* __restrict__ be,
    int layer, int M)
{
    constexpr int F = FOUT;
    __shared__ float Xs[64][64];
    __shared__ float Ws[64][F];
    __shared__ float ssc[128], ssh[128];

    const int tx = threadIdx.x;
    const int ty = threadIdx.y;
    const int tid = ty * 32 + tx;
    const int row0 = blockIdx.x * 64;

    if (tid < 128) {
        const float invN = 1.f / (float)NN;
        float mean = d_sum[layer][tid] * invN;
        float var = d_sumsq[layer][tid] * invN - mean * mean;
        float sc = g[tid] * rsqrtf(var + BN_EPS);
        ssc[tid] = sc;
        ssh[tid] = fmaf(-mean, sc, be[tid]);
    }
    __syncthreads();

    float acc[8][2];
#pragma unroll
    for (int i = 0; i < 8; ++i) { acc[i][0] = 0.f; acc[i][1] = 0.f; }

    for (int kt = 0; kt < 2; ++kt) {
        const int k0 = kt * 64;
        {
            const int nv4 = 64 * F / 4;
            for (int idx = tid; idx < nv4; idx += 256) {
                int r = idx / (F / 4);
                int c4 = idx % (F / 4);
                float4 v = *reinterpret_cast<const float4*>(&W[(k0 + r) * F + c4 * 4]);
                *reinterpret_cast<float4*>(&Ws[r][c4 * 4]) = v;
            }
        }
        {
#pragma unroll
            for (int l = 0; l < 4; ++l) {
                int idx = tid + 256 * l;
                int r = idx >> 4;
                int c4 = idx & 15;
                int grow = row0 + r;
                float4 v = make_float4(0.f, 0.f, 0.f, 0.f);
                if (grow < M) {
                    int2 raw = __ldg(&Xh[grow * 32 + (k0 >> 2) + c4]);
                    float2 f0 = __half22float2(*reinterpret_cast<__half2*>(&raw.x));
                    float2 f1 = __half22float2(*reinterpret_cast<__half2*>(&raw.y));
                    v = make_float4(f0.x, f0.y, f1.x, f1.y);
                }
                int k = k0 + c4 * 4;
                v.x = fmaxf(fmaf(v.x, ssc[k + 0], ssh[k + 0]), 0.f);
                v.y = fmaxf(fmaf(v.y, ssc[k + 1], ssh[k + 1]), 0.f);
                v.z = fmaxf(fmaf(v.z, ssc[k + 2], ssh[k + 2]), 0.f);
                v.w = fmaxf(fmaf(v.w, ssc[k + 3], ssh[k + 3]), 0.f);
                *reinterpret_cast<float4*>(&Xs[r][c4 * 4]) = v;
            }
        }
        __syncthreads();

#pragma unroll 4
        for (int kk = 0; kk < 64; ++kk) {
            float b0 = Ws[kk][tx];
            float b1 = (tx < 8) ? Ws[kk][32 + tx] : 0.f;
#pragma unroll
            for (int i = 0; i < 8; ++i) {
                float a = Xs[ty + 8 * i][kk];
                acc[i][0] = fmaf(a, b0, acc[i][0]);
                acc[i][1] = fmaf(a, b1, acc[i][1]);
            }
        }
        __syncthreads();
    }

#pragma unroll
    for (int i = 0; i < 8; ++i) {
        int grow = row0 + ty + 8 * i;
        if (grow < M) {
            outh[grow * F + tx] = __float2half_rn(acc[i][0]);
            if (tx < 8) outh[grow * F + 32 + tx] = __float2half_rn(acc[i][1]);
        }
    }
}

// ---------------- SpMM F=128 (fp16 gathers, fp16 out) + BN stats tree-reduce ----------------
// int2 at h[col*32 + lane] holds halfs (features) 4*lane .. 4*lane+3.
__global__ __launch_bounds__(256) void spmm128_kernel(
    const int2* __restrict__ h,
    const float* __restrict__ bias,
    int2* __restrict__ outh, int layer, int M)
{
    __shared__ float sacc[8][128];
    const int warp = blockIdx.x * 8 + (threadIdx.x >> 5);
    const int wid = threadIdx.x >> 5;
    const int lane = threadIdx.x & 31;
    const int tid = threadIdx.x;

    float4 acc = make_float4(0.f, 0.f, 0.f, 0.f);
    if (warp < M) {
        const int s = d_rowptr[warp];
        const int e = d_rowptr[warp + 1];
        int base = s;
        for (; base + 32 <= e; base += 32) {
            int2 md = d_ecolw[base + lane];
            int colr = md.x;
            float wr = __int_as_float(md.y);
#pragma unroll
            for (int j = 0; j < 32; ++j) {
                int col = __shfl_sync(0xffffffffu, colr, j);
                float w = __shfl_sync(0xffffffffu, wr, j);
                int2 raw = __ldg(&h[col * 32 + lane]);
                float2 f0 = __half22float2(*reinterpret_cast<__half2*>(&raw.x));
                float2 f1 = __half22float2(*reinterpret_cast<__half2*>(&raw.y));
                acc.x = fmaf(w, f0.x, acc.x);
                acc.y = fmaf(w, f0.y, acc.y);
                acc.z = fmaf(w, f1.x, acc.z);
                acc.w = fmaf(w, f1.y, acc.w);
            }
        }
        if (base < e) {
            int n = e - base;
            int2 md = (lane < n) ? d_ecolw[base + lane] : make_int2(0, 0);
            int colr = md.x;
            float wr = __int_as_float(md.y);
            for (int j = 0; j < n; ++j) {
                int col = __shfl_sync(0xffffffffu, colr, j);
                float w = __shfl_sync(0xffffffffu, wr, j);
                int2 raw = __ldg(&h[col * 32 + lane]);
                float2 f0 = __half22float2(*reinterpret_cast<__half2*>(&raw.x));
                float2 f1 = __half22float2(*reinterpret_cast<__half2*>(&raw.y));
                acc.x = fmaf(w, f0.x, acc.x);
                acc.y = fmaf(w, f0.y, acc.y);
                acc.z = fmaf(w, f1.x, acc.z);
                acc.w = fmaf(w, f1.y, acc.w);
            }
        }
        const int f0i = lane * 4;
        float4 b = *reinterpret_cast<const float4*>(&bias[f0i]);
        acc.x += b.x; acc.y += b.y; acc.z += b.z; acc.w += b.w;
        __half2 h0 = __float22half2_rn(make_float2(acc.x, acc.y));
        __half2 h1 = __float22half2_rn(make_float2(acc.z, acc.w));
        int2 packed;
        packed.x = *reinterpret_cast<int*>(&h0);
        packed.y = *reinterpret_cast<int*>(&h1);
        outh[warp * 32 + lane] = packed;
    }
    // BN stats from fp32 accs: store, tree-reduce, 2 global atomics per feature
    *reinterpret_cast<float4*>(&sacc[wid][lane * 4]) = acc;
    __syncthreads();
    if (tid < 128) {
        float s = 0.f, s2 = 0.f;
#pragma unroll
        for (int w = 0; w < 8; ++w) {
            float v = sacc[w][tid];
            s += v;
            s2 = fmaf(v, v, s2);
        }
        atomicAdd(&d_sum[layer][tid], s);
        atomicAdd(&d_sumsq[layer][tid], s2);
    }
}

// ---------------- SpMM F=40 (fp16 gathers, fp32 accum & output) ----------------
__global__ __launch_bounds__(256) void spmm40_kernel(
    const __half2* __restrict__ h,
    const float* __restrict__ bias,
    float* __restrict__ out, int M)
{
    const int warp = blockIdx.x * 8 + (threadIdx.x >> 5);
    const int lane = threadIdx.x & 31;
    if (warp >= M) return;
    const int s = d_rowptr[warp];
    const int e = d_rowptr[warp + 1];

    float2 acc = make_float2(0.f, 0.f);
    int base = s;
    for (; base + 32 <= e; base += 32) {
        int2 md = d_ecolw[base + lane];
        int colr = md.x;
        float wr = __int_as_float(md.y);
#pragma unroll
        for (int j = 0; j < 32; ++j) {
            int col = __shfl_sync(0xffffffffu, colr, j);
            float w = __shfl_sync(0xffffffffu, wr, j);
            if (lane < 20) {
                float2 v = __half22float2(__ldg(&h[col * 20 + lane]));
                acc.x = fmaf(w, v.x, acc.x);
                acc.y = fmaf(w, v.y, acc.y);
            }
        }
    }
    if (base < e) {
        int n = e - base;
        int2 md = (lane < n) ? d_ecolw[base + lane] : make_int2(0, 0);
        int colr = md.x;
        float wr = __int_as_float(md.y);
        for (int j = 0; j < n; ++j) {
            int col = __shfl_sync(0xffffffffu, colr, j);
            float w = __shfl_sync(0xffffffffu, wr, j);
            if (lane < 20) {
                float2 v = __half22float2(__ldg(&h[col * 20 + lane]));
                acc.x = fmaf(w, v.x, acc.x);
                acc.y = fmaf(w, v.y, acc.y);
            }
        }
    }
    if (lane < 20) {
        acc.x += bias[2 * lane];
        acc.y += bias[2 * lane + 1];
        *reinterpret_cast<float2*>(&out[warp * FOUT + 2 * lane]) = acc;
    }
}

// ---------------- launch ----------------
extern "C" void kernel_launch(void* const* d_in, const int* in_sizes, int n_in,
                              void* d_out, int out_size)
{
    const float* x   = (const float*)d_in[0];
    const int*   er  = (const int*)d_in[1];
    const int*   ec  = (const int*)d_in[2];
    const float* ew  = (const float*)d_in[3];
    const float* W0  = (const float*)d_in[4];
    const float* b0  = (const float*)d_in[5];
    const float* g0  = (const float*)d_in[6];
    const float* be0 = (const float*)d_in[7];
    const float* W1  = (const float*)d_in[8];
    const float* b1  = (const float*)d_in[9];
    const float* g1  = (const float*)d_in[10];
    const float* be1 = (const float*)d_in[11];
    const float* W2  = (const float*)d_in[12];
    const float* b2  = (const float*)d_in[13];
    float* out = (float*)d_out;

    const int M = in_sizes[0] / FIN;
    const int E = in_sizes[1];

    int2*   t0h; cudaGetSymbolAddress((void**)&t0h, d_t0h);
    int2*   t1h; cudaGetSymbolAddress((void**)&t1h, d_t1h);
    __half* t2h; cudaGetSymbolAddress((void**)&t2h, d_t2h);

    const int g128 = (M + 127) / 128;
    const int gsp  = (M + 7) / 8;
    const int E4   = (E + 3) / 4;
    const int hB   = (E4 + 255) / 256;

    // zero counts + BN sums
    zero_kernel<<<(NN + 255) / 256, 256>>>();
    // fused: gemm128 layer-0 (blocks [0,g128)) parallel with hist (rest)
    fused0_kernel<<<g128 + hB, 256>>>(x, W0, (__half2*)t0h, er, E, M, g128);
    scan_kernel<<<1, 1024>>>(M);
    scatter_kernel<<<hB, 256>>>(er, ec, ew, E);

    // layer 0 aggregate
    spmm128_kernel<<<gsp, 256>>>(t0h, b0, t1h, 0, M);

    // layer 1 (BN finalize of layer-0 stats fused into gemm prologue)
    gemm128h_kernel<<<g128, 256>>>(t1h, W1, (__half2*)t0h, g0, be0, 0, M);
    spmm128_kernel<<<gsp, 256>>>(t0h, b1, t1h, 1, M);

    // layer 2 (BN finalize of layer-1 stats fused into gemm40 prologue)
    gemm40_kernel<<<(M + 63) / 64, dim3(32, 8)>>>(t1h, W2, t2h, g1, be1, 1, M);
    spmm40_kernel<<<gsp, 256>>>((const __half2*)t2h, b2, out, M);
}

// round 14
// speedup vs baseline: 2.0013x; 1.0356x over previous
#include <cuda_runtime.h>
#include <cuda_bf16.h>
#include <cuda_fp16.h>
#include <cstdint>

#define NN 50000
#define FIN 128
#define FOUT 40
#define EMAX 1600000
#define BN_EPS 1e-5f

// ---------------- device scratch ----------------
__device__ int2   d_t0h[NN * 32];           // fp16 gemm output (128 halfs = 32 int2 per row)
__device__ int2   d_t1h[NN * 32];           // fp16 spmm output (activations)
__device__ __half d_t2h[NN * FOUT + 64];    // fp16 layer-2 gemm output
__device__ int2   d_ecolw[EMAX];
__device__ int    d_epos[EMAX];
__device__ int    d_counts[NN];
__device__ int    d_rowptr[NN + 1];
__device__ float  d_sum[2][FIN];
__device__ float  d_sumsq[2][FIN];

// ---------------- CSR build pieces ----------------
__global__ void zero_kernel() {
    int i = blockIdx.x * blockDim.x + threadIdx.x;
    if (i < NN) d_counts[i] = 0;
    if (i < FIN) {
        d_sum[0][i] = 0.f; d_sum[1][i] = 0.f;
        d_sumsq[0][i] = 0.f; d_sumsq[1][i] = 0.f;
    }
}

__device__ __forceinline__ void hist_body(const int* __restrict__ er, int E, int bid) {
    int i = bid * 256 + threadIdx.x;
    int e = i * 4;
    if (e + 4 <= E) {
        int4 r = *reinterpret_cast<const int4*>(&er[e]);
        int4 p;
        p.x = atomicAdd(&d_counts[r.x], 1);
        p.y = atomicAdd(&d_counts[r.y], 1);
        p.z = atomicAdd(&d_counts[r.z], 1);
        p.w = atomicAdd(&d_counts[r.w], 1);
        *reinterpret_cast<int4*>(&d_epos[e]) = p;
    } else {
        for (; e < E; ++e) d_epos[e] = atomicAdd(&d_counts[er[e]], 1);
    }
}

__global__ void scan_kernel(int Nn) {
    __shared__ int ssum[1024];
    int t = threadIdx.x;
    int chunk = (Nn + 1023) >> 10;
    int base = t * chunk;
    int s = 0;
    for (int i = 0; i < chunk; ++i) {
        int idx = base + i;
        if (idx < Nn) s += d_counts[idx];
    }
    ssum[t] = s;
    __syncthreads();
    for (int off = 1; off < 1024; off <<= 1) {
        int v = (t >= off) ? ssum[t - off] : 0;
        __syncthreads();
        ssum[t] += v;
        __syncthreads();
    }
    int run = (t > 0) ? ssum[t - 1] : 0;
    for (int i = 0; i < chunk; ++i) {
        int idx = base + i;
        if (idx < Nn) {
            d_rowptr[idx] = run;
            run += d_counts[idx];
        }
    }
    if (t == 1023) d_rowptr[Nn] = run;
}

__global__ void scatter_kernel(const int* __restrict__ er, const int* __restrict__ ec,
                               const float* __restrict__ ew, int E) {
    int i = blockIdx.x * blockDim.x + threadIdx.x;
    int e = i * 4;
    if (e + 4 <= E) {
        int4 r = *reinterpret_cast<const int4*>(&er[e]);
        int4 c = *reinterpret_cast<const int4*>(&ec[e]);
        float4 w = *reinterpret_cast<const float4*>(&ew[e]);
        int4 p = *reinterpret_cast<const int4*>(&d_epos[e]);
        d_ecolw[d_rowptr[r.x] + p.x] = make_int2(c.x, __float_as_int(w.x));
        d_ecolw[d_rowptr[r.y] + p.y] = make_int2(c.y, __float_as_int(w.y));
        d_ecolw[d_rowptr[r.z] + p.z] = make_int2(c.z, __float_as_int(w.z));
        d_ecolw[d_rowptr[r.w] + p.w] = make_int2(c.w, __float_as_int(w.w));
    } else {
        for (; e < E; ++e) {
            int pos = d_rowptr[er[e]] + d_epos[e];
            d_ecolw[pos] = make_int2(ec[e], __float_as_int(ew[e]));
        }
    }
}

// ---------------- fp16-split helpers ----------------
__device__ __forceinline__ void h16_split(float a, __half& hi, __half& lo) {
    hi = __float2half_rn(a);
    lo = __float2half_rn(a - __half2float(hi));
}

__device__ __forceinline__ uint32_t pack_h2(__half a, __half b) {
    __half2 h = __halves2half2(a, b);   // .x = a (low, even k), .y = b (high, odd k)
    return *reinterpret_cast<uint32_t*>(&h);
}

__device__ __forceinline__ void mma_f16(float* c, const uint32_t* a, uint32_t b0, uint32_t b1) {
    asm volatile("mma.sync.aligned.m16n8k16.row.col.f32.f16.f16.f32 "
        "{%0,%1,%2,%3}, {%4,%5,%6,%7}, {%8,%9}, {%0,%1,%2,%3};"
        : "+f"(c[0]), "+f"(c[1]), "+f"(c[2]), "+f"(c[3])
        : "r"(a[0]), "r"(a[1]), "r"(a[2]), "r"(a[3]), "r"(b0), "r"(b1));
}

// ---------------- GEMM 128x128 body (split-fp16 m16n8k16, fp16 output) ----------------
// XH: X is fp16 (int2-packed, 32 int2 per row); else fp32.
// D = X@W with X = Xhi+Xlo, W = Whi+Wlo (fp16 pairs): ahi*bhi + alo*bhi + ahi*blo.
template <bool BN, bool XH>
__device__ __forceinline__ void gemm128_body(
    const void* __restrict__ Xv, const float* __restrict__ W,
    __half2* __restrict__ outh,
    const float* __restrict__ g, const float* __restrict__ be,
    int layer, int M, int bid)
{
    __shared__ uint32_t Xhi[128][18], Xlo[128][18];   // [row][k2] half2-as-u32, 16 used + pad
    __shared__ uint32_t Whi[128][18], Wlo[128][18];   // [n][k2] (transposed W chunk)
    __shared__ float ssc[128], ssh[128];

    const float* __restrict__ Xf = (const float*)Xv;
    const int2* __restrict__ Xh = (const int2*)Xv;

    const int tid = threadIdx.x;
    const int lane = tid & 31;
    const int warp = tid >> 5;
    const int gid = lane >> 2;
    const int tig = lane & 3;
    const int wm = warp >> 1;
    const int wn = warp & 1;
    const int row0 = bid * 128;

    if (BN) {
        if (tid < 128) {
            const float invN = 1.f / (float)NN;
            float mean = d_sum[layer][tid] * invN;
            float var = d_sumsq[layer][tid] * invN - mean * mean;
            float sc = g[tid] * rsqrtf(var + BN_EPS);
            ssc[tid] = sc;
            ssh[tid] = fmaf(-mean, sc, be[tid]);
        }
        __syncthreads();
    }

    float c[2][8][4];
#pragma unroll
    for (int mt = 0; mt < 2; ++mt)
#pragma unroll
        for (int nt = 0; nt < 8; ++nt)
#pragma unroll
            for (int q = 0; q < 4; ++q) c[mt][nt][q] = 0.f;

    for (int kt = 0; kt < 4; ++kt) {
        const int k0 = kt * 32;
        // W chunk transpose + split: entries (n in [0,128), k2 in [0,16))
#pragma unroll
        for (int l = 0; l < 8; ++l) {
            int idx = tid + 256 * l;
            int n = idx & 127;
            int k2 = idx >> 7;
            float w0 = W[(k0 + 2 * k2) * 128 + n];
            float w1 = W[(k0 + 2 * k2 + 1) * 128 + n];
            __half h0, l0, h1, l1;
            h16_split(w0, h0, l0);
            h16_split(w1, h1, l1);
            Whi[n][k2] = pack_h2(h0, h1);
            Wlo[n][k2] = pack_h2(l0, l1);
        }
        // X chunk load (+BN) + split: entries (r in [0,128), c4 in [0,8)) covering k 4c4..4c4+3
#pragma unroll
        for (int l = 0; l < 4; ++l) {
            int idx = tid + 256 * l;
            int r = idx >> 3;
            int c4 = idx & 7;
            int grow = row0 + r;
            float4 v = make_float4(0.f, 0.f, 0.f, 0.f);
            if (grow < M) {
                if (XH) {
                    int2 raw = __ldg(&Xh[grow * 32 + (k0 >> 2) + c4]);
                    float2 f0 = __half22float2(*reinterpret_cast<__half2*>(&raw.x));
                    float2 f1 = __half22float2(*reinterpret_cast<__half2*>(&raw.y));
                    v = make_float4(f0.x, f0.y, f1.x, f1.y);
                } else {
                    v = *reinterpret_cast<const float4*>(&Xf[grow * 128 + k0 + c4 * 4]);
                }
            }
            if (BN) {
                int k = k0 + c4 * 4;
                v.x = fmaxf(fmaf(v.x, ssc[k + 0], ssh[k + 0]), 0.f);
                v.y = fmaxf(fmaf(v.y, ssc[k + 1], ssh[k + 1]), 0.f);
                v.z = fmaxf(fmaf(v.z, ssc[k + 2], ssh[k + 2]), 0.f);
                v.w = fmaxf(fmaf(v.w, ssc[k + 3], ssh[k + 3]), 0.f);
            }
            __half hx, lx, hy, ly, hz, lz, hw, lw;
            h16_split(v.x, hx, lx);
            h16_split(v.y, hy, ly);
            h16_split(v.z, hz, lz);
            h16_split(v.w, hw, lw);
            Xhi[r][c4 * 2 + 0] = pack_h2(hx, hy);
            Xhi[r][c4 * 2 + 1] = pack_h2(hz, hw);
            Xlo[r][c4 * 2 + 0] = pack_h2(lx, ly);
            Xlo[r][c4 * 2 + 1] = pack_h2(lz, lw);
        }
        __syncthreads();

        // two k16 MMA steps per 32-k chunk
#pragma unroll
        for (int ks2 = 0; ks2 < 16; ks2 += 8) {
            uint32_t ahi[2][4], alo[2][4];
#pragma unroll
            for (int mt = 0; mt < 2; ++mt) {
                int rb = wm * 32 + mt * 16;
                ahi[mt][0] = Xhi[rb + gid][ks2 + tig];
                ahi[mt][1] = Xhi[rb + gid + 8][ks2 + tig];
                ahi[mt][2] = Xhi[rb + gid][ks2 + tig + 4];
                ahi[mt][3] = Xhi[rb + gid + 8][ks2 + tig + 4];
                alo[mt][0] = Xlo[rb + gid][ks2 + tig];
                alo[mt][1] = Xlo[rb + gid + 8][ks2 + tig];
                alo[mt][2] = Xlo[rb + gid][ks2 + tig + 4];
                alo[mt][3] = Xlo[rb + gid + 8][ks2 + tig + 4];
            }
#pragma unroll
            for (int nt = 0; nt < 8; ++nt) {
                int ncol = wn * 64 + nt * 8 + gid;
                uint32_t bh0 = Whi[ncol][ks2 + tig];
                uint32_t bh1 = Whi[ncol][ks2 + tig + 4];
                uint32_t bl0 = Wlo[ncol][ks2 + tig];
                uint32_t bl1 = Wlo[ncol][ks2 + tig + 4];
#pragma unroll
                for (int mt = 0; mt < 2; ++mt) {
                    mma_f16(c[mt][nt], ahi[mt], bh0, bh1);
                    mma_f16(c[mt][nt], alo[mt], bh0, bh1);
                    mma_f16(c[mt][nt], ahi[mt], bl0, bl1);
                }
            }
        }
        __syncthreads();
    }

    // fp16 epilogue: half index == feature index (linear row layout)
#pragma unroll
    for (int mt = 0; mt < 2; ++mt) {
#pragma unroll
        for (int nt = 0; nt < 8; ++nt) {
            int col = wn * 64 + nt * 8 + 2 * tig;
            int r0 = row0 + wm * 32 + mt * 16 + gid;
            if (r0 < M)
                outh[r0 * 64 + (col >> 1)] =
                    __float22half2_rn(make_float2(c[mt][nt][0], c[mt][nt][1]));
            if (r0 + 8 < M)
                outh[(r0 + 8) * 64 + (col >> 1)] =
                    __float22half2_rn(make_float2(c[mt][nt][2], c[mt][nt][3]));
        }
    }
}

// fused front: blocks [0,gB) run gemm128 layer-0, the rest run hist
__global__ __launch_bounds__(256) void fused0_kernel(
    const float* __restrict__ x, const float* __restrict__ W0,
    __half2* __restrict__ outh, const int* __restrict__ er,
    int E, int M, int gB)
{
    if ((int)blockIdx.x < gB)
        gemm128_body<false, false>(x, W0, outh, nullptr, nullptr, 0, M, blockIdx.x);
    else
        hist_body(er, E, blockIdx.x - gB);
}

__global__ __launch_bounds__(256) void gemm128h_kernel(
    const int2* __restrict__ X, const float* __restrict__ W,
    __half2* __restrict__ outh,
    const float* __restrict__ g, const float* __restrict__ be,
    int layer, int M)
{
    gemm128_body<true, true>(X, W, outh, g, be, layer, M, blockIdx.x);
}

// ---------------- GEMM F=40 (fp16 in, fp32 compute, fp16 out, BN fused) ----------------
__global__ __launch_bounds__(256) void gemm40_kernel(
    const int2* __restrict__ Xh, const float* __restrict__ W,
    __half* __restrict__ outh,
    const float* __restrict__ g, const float* __restrict__ be,
    int layer, int M)
{
    constexpr int F = FOUT;
    __shared__ float Xs[64][64];
    __shared__ float Ws[64][F];
    __shared__ float ssc[128], ssh[128];

    const int tx = threadIdx.x;
    const int ty = threadIdx.y;
    const int tid = ty * 32 + tx;
    const int row0 = blockIdx.x * 64;

    if (tid < 128) {
        const float invN = 1.f / (float)NN;
        float mean = d_sum[layer][tid] * invN;
        float var = d_sumsq[layer][tid] * invN - mean * mean;
        float sc = g[tid] * rsqrtf(var + BN_EPS);
        ssc[tid] = sc;
        ssh[tid] = fmaf(-mean, sc, be[tid]);
    }
    __syncthreads();

    float acc[8][2];
#pragma unroll
    for (int i = 0; i < 8; ++i) { acc[i][0] = 0.f; acc[i][1] = 0.f; }

    for (int kt = 0; kt < 2; ++kt) {
        const int k0 = kt * 64;
        {
            const int nv4 = 64 * F / 4;
            for (int idx = tid; idx < nv4; idx += 256) {
                int r = idx / (F / 4);
                int c4 = idx % (F / 4);
                float4 v = *reinterpret_cast<const float4*>(&W[(k0 + r) * F + c4 * 4]);
                *reinterpret_cast<float4*>(&Ws[r][c4 * 4]) = v;
            }
        }
        {
#pragma unroll
            for (int l = 0; l < 4; ++l) {
                int idx = tid + 256 * l;
                int r = idx >> 4;
                int c4 = idx & 15;
                int grow = row0 + r;
                float4 v = make_float4(0.f, 0.f, 0.f, 0.f);
                if (grow < M) {
                    int2 raw = __ldg(&Xh[grow * 32 + (k0 >> 2) + c4]);
                    float2 f0 = __half22float2(*reinterpret_cast<__half2*>(&raw.x));
                    float2 f1 = __half22float2(*reinterpret_cast<__half2*>(&raw.y));
                    v = make_float4(f0.x, f0.y, f1.x, f1.y);
                }
                int k = k0 + c4 * 4;
                v.x = fmaxf(fmaf(v.x, ssc[k + 0], ssh[k + 0]), 0.f);
                v.y = fmaxf(fmaf(v.y, ssc[k + 1], ssh[k + 1]), 0.f);
                v.z = fmaxf(fmaf(v.z, ssc[k + 2], ssh[k + 2]), 0.f);
                v.w = fmaxf(fmaf(v.w, ssc[k + 3], ssh[k + 3]), 0.f);
                *reinterpret_cast<float4*>(&Xs[r][c4 * 4]) = v;
            }
        }
        __syncthreads();

#pragma unroll 4
        for (int kk = 0; kk < 64; ++kk) {
            float b0 = Ws[kk][tx];
            float b1 = (tx < 8) ? Ws[kk][32 + tx] : 0.f;
#pragma unroll
            for (int i = 0; i < 8; ++i) {
                float a = Xs[ty + 8 * i][kk];
                acc[i][0] = fmaf(a, b0, acc[i][0]);
                acc[i][1] = fmaf(a, b1, acc[i][1]);
            }
        }
        __syncthreads();
    }

#pragma unroll
    for (int i = 0; i < 8; ++i) {
        int grow = row0 + ty + 8 * i;
        if (grow < M) {
            outh[grow * F + tx] = __float2half_rn(acc[i][0]);
            if (tx < 8) outh[grow * F + 32 + tx] = __float2half_rn(acc[i][1]);
        }
    }
}

// ---------------- SpMM F=128 (fp16 gathers, fp16 out) + BN stats tree-reduce ----------------
// int2 at h[col*32 + lane] holds halfs (features) 4*lane .. 4*lane+3.
__global__ __launch_bounds__(256) void spmm128_kernel(
    const int2* __restrict__ h,
    const float* __restrict__ bias,
    int2* __restrict__ outh, int layer, int M)
{
    __shared__ float sacc[8][128];
    const int warp = blockIdx.x * 8 + (threadIdx.x >> 5);
    const int wid = threadIdx.x >> 5;
    const int lane = threadIdx.x & 31;
    const int tid = threadIdx.x;

    float4 acc = make_float4(0.f, 0.f, 0.f, 0.f);
    if (warp < M) {
        const int s = d_rowptr[warp];
        const int e = d_rowptr[warp + 1];
        int base = s;
        for (; base + 32 <= e; base += 32) {
            int2 md = d_ecolw[base + lane];
            int colr = md.x;
            float wr = __int_as_float(md.y);
#pragma unroll
            for (int j = 0; j < 32; ++j) {
                int col = __shfl_sync(0xffffffffu, colr, j);
                float w = __shfl_sync(0xffffffffu, wr, j);
                int2 raw = __ldg(&h[col * 32 + lane]);
                float2 f0 = __half22float2(*reinterpret_cast<__half2*>(&raw.x));
                float2 f1 = __half22float2(*reinterpret_cast<__half2*>(&raw.y));
                acc.x = fmaf(w, f0.x, acc.x);
                acc.y = fmaf(w, f0.y, acc.y);
                acc.z = fmaf(w, f1.x, acc.z);
                acc.w = fmaf(w, f1.y, acc.w);
            }
        }
        if (base < e) {
            int n = e - base;
            int2 md = (lane < n) ? d_ecolw[base + lane] : make_int2(0, 0);
            int colr = md.x;
            float wr = __int_as_float(md.y);
            for (int j = 0; j < n; ++j) {
                int col = __shfl_sync(0xffffffffu, colr, j);
                float w = __shfl_sync(0xffffffffu, wr, j);
                int2 raw = __ldg(&h[col * 32 + lane]);
                float2 f0 = __half22float2(*reinterpret_cast<__half2*>(&raw.x));
                float2 f1 = __half22float2(*reinterpret_cast<__half2*>(&raw.y));
                acc.x = fmaf(w, f0.x, acc.x);
                acc.y = fmaf(w, f0.y, acc.y);
                acc.z = fmaf(w, f1.x, acc.z);
                acc.w = fmaf(w, f1.y, acc.w);
            }
        }
        const int f0i = lane * 4;
        float4 b = *reinterpret_cast<const float4*>(&bias[f0i]);
        acc.x += b.x; acc.y += b.y; acc.z += b.z; acc.w += b.w;
        __half2 h0 = __float22half2_rn(make_float2(acc.x, acc.y));
        __half2 h1 = __float22half2_rn(make_float2(acc.z, acc.w));
        int2 packed;
        packed.x = *reinterpret_cast<int*>(&h0);
        packed.y = *reinterpret_cast<int*>(&h1);
        outh[warp * 32 + lane] = packed;
    }
    // BN stats from fp32 accs: store, tree-reduce, 2 global atomics per feature
    *reinterpret_cast<float4*>(&sacc[wid][lane * 4]) = acc;
    __syncthreads();
    if (tid < 128) {
        float s = 0.f, s2 = 0.f;
#pragma unroll
        for (int w = 0; w < 8; ++w) {
            float v = sacc[w][tid];
            s += v;
            s2 = fmaf(v, v, s2);
        }
        atomicAdd(&d_sum[layer][tid], s);
        atomicAdd(&d_sumsq[layer][tid], s2);
    }
}

// ---------------- SpMM F=40 (fp16 gathers, fp32 accum & output) ----------------
__global__ __launch_bounds__(256) void spmm40_kernel(
    const __half2* __restrict__ h,
    const float* __restrict__ bias,
    float* __restrict__ out, int M)
{
    const int warp = blockIdx.x * 8 + (threadIdx.x >> 5);
    const int lane = threadIdx.x & 31;
    if (warp >= M) return;
    const int s = d_rowptr[warp];
    const int e = d_rowptr[warp + 1];

    float2 acc = make_float2(0.f, 0.f);
    int base = s;
    for (; base + 32 <= e; base += 32) {
        int2 md = d_ecolw[base + lane];
        int colr = md.x;
        float wr = __int_as_float(md.y);
#pragma unroll
        for (int j = 0; j < 32; ++j) {
            int col = __shfl_sync(0xffffffffu, colr, j);
            float w = __shfl_sync(0xffffffffu, wr, j);
            if (lane < 20) {
                float2 v = __half22float2(__ldg(&h[col * 20 + lane]));
                acc.x = fmaf(w, v.x, acc.x);
                acc.y = fmaf(w, v.y, acc.y);
            }
        }
    }
    if (base < e) {
        int n = e - base;
        int2 md = (lane < n) ? d_ecolw[base + lane] : make_int2(0, 0);
        int colr = md.x;
        float wr = __int_as_float(md.y);
        for (int j = 0; j < n; ++j) {
            int col = __shfl_sync(0xffffffffu, colr, j);
            float w = __shfl_sync(0xffffffffu, wr, j);
            if (lane < 20) {
                float2 v = __half22float2(__ldg(&h[col * 20 + lane]));
                acc.x = fmaf(w, v.x, acc.x);
                acc.y = fmaf(w, v.y, acc.y);
            }
        }
    }
    if (lane < 20) {
        acc.x += bias[2 * lane];
        acc.y += bias[2 * lane + 1];
        *reinterpret_cast<float2*>(&out[warp * FOUT + 2 * lane]) = acc;
    }
}

// ---------------- launch ----------------
extern "C" void kernel_launch(void* const* d_in, const int* in_sizes, int n_in,
                              void* d_out, int out_size)
{
    const float* x   = (const float*)d_in[0];
    const int*   er  = (const int*)d_in[1];
    const int*   ec  = (const int*)d_in[2];
    const float* ew  = (const float*)d_in[3];
    const float* W0  = (const float*)d_in[4];
    const float* b0  = (const float*)d_in[5];
    const float* g0  = (const float*)d_in[6];
    const float* be0 = (const float*)d_in[7];
    const float* W1  = (const float*)d_in[8];
    const float* b1  = (const float*)d_in[9];
    const float* g1  = (const float*)d_in[10];
    const float* be1 = (const float*)d_in[11];
    const float* W2  = (const float*)d_in[12];
    const float* b2  = (const float*)d_in[13];
    float* out = (float*)d_out;

    const int M = in_sizes[0] / FIN;
    const int E = in_sizes[1];

    int2*   t0h; cudaGetSymbolAddress((void**)&t0h, d_t0h);
    int2*   t1h; cudaGetSymbolAddress((void**)&t1h, d_t1h);
    __half* t2h; cudaGetSymbolAddress((void**)&t2h, d_t2h);

    const int g128 = (M + 127) / 128;
    const int gsp  = (M + 7) / 8;
    const int E4   = (E + 3) / 4;
    const int hB   = (E4 + 255) / 256;

    // zero counts + BN sums
    zero_kernel<<<(NN + 255) / 256, 256>>>();
    // fused: gemm128 layer-0 (blocks [0,g128)) parallel with hist (rest)
    fused0_kernel<<<g128 + hB, 256>>>(x, W0, (__half2*)t0h, er, E, M, g128);
    scan_kernel<<<1, 1024>>>(M);
    scatter_kernel<<<hB, 256>>>(er, ec, ew, E);

    // layer 0 aggregate
    spmm128_kernel<<<gsp, 256>>>(t0h, b0, t1h, 0, M);

    // layer 1 (BN finalize of layer-0 stats fused into gemm prologue)
    gemm128h_kernel<<<g128, 256>>>(t1h, W1, (__half2*)t0h, g0, be0, 0, M);
    spmm128_kernel<<<gsp, 256>>>(t0h, b1, t1h, 1, M);

    // layer 2 (BN finalize of layer-1 stats fused into gemm40 prologue)
    gemm40_kernel<<<(M + 63) / 64, dim3(32, 8)>>>(t1h, W2, t2h, g1, be1, 1, M);
    spmm40_kernel<<<gsp, 256>>>((const __half2*)t2h, b2, out, M);
}

// round 16
// speedup vs baseline: 2.0491x; 1.0239x over previous
#include <cuda_runtime.h>
#include <cuda_bf16.h>
#include <cuda_fp16.h>
#include <cstdint>

#define NN 50000
#define FIN 128
#define FOUT 40
#define EMAX 1600000
#define BN_EPS 1e-5f

// ---------------- device scratch ----------------
__device__ int2     d_t0h[NN * 32];           // fp16 gemm output (128 halfs = 32 int2 per row)
__device__ int2     d_t1h[NN * 32];           // fp16 spmm output (activations)
__device__ __half   d_t2h[NN * FOUT + 64];    // fp16 layer-2 gemm output
__device__ int2     d_ecolw[EMAX];
__device__ int      d_epos[EMAX];
__device__ int      d_counts[NN];
__device__ int      d_rowptr[NN + 1];
__device__ float    d_sum[2][FIN];
__device__ float    d_sumsq[2][FIN];
__device__ uint32_t d_Whi[2 * 4 * 128 * 16];  // pre-split W (hi), [layer][kt][n][k2]
__device__ uint32_t d_Wlo[2 * 4 * 128 * 16];  // pre-split W (lo)

// ---------------- fp16-split helpers ----------------
__device__ __forceinline__ void h16_split(float a, __half& hi, __half& lo) {
    hi = __float2half_rn(a);
    lo = __float2half_rn(a - __half2float(hi));
}

__device__ __forceinline__ uint32_t pack_h2(__half a, __half b) {
    __half2 h = __halves2half2(a, b);
    return *reinterpret_cast<uint32_t*>(&h);
}

__device__ __forceinline__ void mma_f16(float* c, const uint32_t* a, uint32_t b0, uint32_t b1) {
    asm volatile("mma.sync.aligned.m16n8k16.row.col.f32.f16.f16.f32 "
        "{%0,%1,%2,%3}, {%4,%5,%6,%7}, {%8,%9}, {%0,%1,%2,%3};"
        : "+f"(c[0]), "+f"(c[1]), "+f"(c[2]), "+f"(c[3])
        : "r"(a[0]), "r"(a[1]), "r"(a[2]), "r"(a[3]), "r"(b0), "r"(b1));
}

// ---------------- zero + W pre-split ----------------
// W split layout: index ((layer*4+kt)*128+n)*16+k2; entry = halves (k0+2k2, k0+2k2+1) of col n.
// Per-layer region size = 4*128*16 = 8192 = 2^13 entries.
__global__ void zero_kernel(const float* __restrict__ W0, const float* __restrict__ W1) {
    int i = blockIdx.x * blockDim.x + threadIdx.x;
    if (i < NN) d_counts[i] = 0;
    if (i < FIN) {
        d_sum[0][i] = 0.f; d_sum[1][i] = 0.f;
        d_sumsq[0][i] = 0.f; d_sumsq[1][i] = 0.f;
    }
    if (i < 2 * 4 * 128 * 16) {
        int layer = i >> 13;          // FIX: 8192 entries per layer
        int r = i & 8191;             // FIX
        int kt = r >> 11;             // [0,4)
        int e = r & 2047;
        int n = e >> 4;
        int k2 = e & 15;
        const float* W = layer ? W1 : W0;
        float w0 = W[(kt * 32 + 2 * k2) * 128 + n];
        float w1 = W[(kt * 32 + 2 * k2 + 1) * 128 + n];
        __half h0, l0, h1, l1;
        h16_split(w0, h0, l0);
        h16_split(w1, h1, l1);
        d_Whi[i] = pack_h2(h0, h1);
        d_Wlo[i] = pack_h2(l0, l1);
    }
}

// ---------------- CSR build pieces ----------------
__device__ __forceinline__ void hist_body(const int* __restrict__ er, int E, int bid) {
    int i = bid * 256 + threadIdx.x;
    int e = i * 4;
    if (e + 4 <= E) {
        int4 r = *reinterpret_cast<const int4*>(&er[e]);
        int4 p;
        p.x = atomicAdd(&d_counts[r.x], 1);
        p.y = atomicAdd(&d_counts[r.y], 1);
        p.z = atomicAdd(&d_counts[r.z], 1);
        p.w = atomicAdd(&d_counts[r.w], 1);
        *reinterpret_cast<int4*>(&d_epos[e]) = p;
    } else {
        for (; e < E; ++e) d_epos[e] = atomicAdd(&d_counts[er[e]], 1);
    }
}

__device__ __forceinline__ void scatter_body(const int* __restrict__ er, const int* __restrict__ ec,
                                             const float* __restrict__ ew, int E, int bid) {
    int i = bid * 256 + threadIdx.x;
    int e = i * 4;
    if (e + 4 <= E) {
        int4 r = *reinterpret_cast<const int4*>(&er[e]);
        int4 c = *reinterpret_cast<const int4*>(&ec[e]);
        float4 w = *reinterpret_cast<const float4*>(&ew[e]);
        int4 p = *reinterpret_cast<const int4*>(&d_epos[e]);
        d_ecolw[d_rowptr[r.x] + p.x] = make_int2(c.x, __float_as_int(w.x));
        d_ecolw[d_rowptr[r.y] + p.y] = make_int2(c.y, __float_as_int(w.y));
        d_ecolw[d_rowptr[r.z] + p.z] = make_int2(c.z, __float_as_int(w.z));
        d_ecolw[d_rowptr[r.w] + p.w] = make_int2(c.w, __float_as_int(w.w));
    } else {
        for (; e < E; ++e) {
            int pos = d_rowptr[er[e]] + d_epos[e];
            d_ecolw[pos] = make_int2(ec[e], __float_as_int(ew[e]));
        }
    }
}

__global__ void scan_kernel(int Nn) {
    __shared__ int ssum[1024];
    int t = threadIdx.x;
    int chunk = (Nn + 1023) >> 10;
    int base = t * chunk;
    int s = 0;
    for (int i = 0; i < chunk; ++i) {
        int idx = base + i;
        if (idx < Nn) s += d_counts[idx];
    }
    ssum[t] = s;
    __syncthreads();
    for (int off = 1; off < 1024; off <<= 1) {
        int v = (t >= off) ? ssum[t - off] : 0;
        __syncthreads();
        ssum[t] += v;
        __syncthreads();
    }
    int run = (t > 0) ? ssum[t - 1] : 0;
    for (int i = 0; i < chunk; ++i) {
        int idx = base + i;
        if (idx < Nn) {
            d_rowptr[idx] = run;
            run += d_counts[idx];
        }
    }
    if (t == 1023) d_rowptr[Nn] = run;
}

// ---------------- GEMM 128x128 body (split-fp16 m16n8k16, pre-split W, fp16 out) ----------------
// XH: X is fp16 (int2-packed); else fp32. wlayer selects pre-split weights.
template <bool BN, bool XH>
__device__ __forceinline__ void gemm128_body(
    const void* __restrict__ Xv,
    __half2* __restrict__ outh,
    const float* __restrict__ g, const float* __restrict__ be,
    int wlayer, int layer, int M, int bid)
{
    __shared__ uint32_t Xhi[128][18], Xlo[128][18];   // [row][k2], +pad
    __shared__ uint32_t Whs[128][20], Wls[128][20];   // [n][k2], stride 20 (16B-aligned uint4)
    __shared__ float ssc[128], ssh[128];

    const float* __restrict__ Xf = (const float*)Xv;
    const int2* __restrict__ Xh = (const int2*)Xv;

    const int tid = threadIdx.x;
    const int lane = tid & 31;
    const int warp = tid >> 5;
    const int gid = lane >> 2;
    const int tig = lane & 3;
    const int wm = warp >> 1;
    const int wn = warp & 1;
    const int row0 = bid * 128;

    if (BN) {
        if (tid < 128) {
            const float invN = 1.f / (float)NN;
            float mean = d_sum[layer][tid] * invN;
            float var = d_sumsq[layer][tid] * invN - mean * mean;
            float sc = g[tid] * rsqrtf(var + BN_EPS);
            ssc[tid] = sc;
            ssh[tid] = fmaf(-mean, sc, be[tid]);
        }
        __syncthreads();
    }

    float c[2][8][4];
#pragma unroll
    for (int mt = 0; mt < 2; ++mt)
#pragma unroll
        for (int nt = 0; nt < 8; ++nt)
#pragma unroll
            for (int q = 0; q < 4; ++q) c[mt][nt][q] = 0.f;

    for (int kt = 0; kt < 4; ++kt) {
        const int k0 = kt * 32;
        // W chunk: direct coalesced uint4 loads of pre-split data
        {
            const uint32_t* __restrict__ Whg = d_Whi + (wlayer * 4 + kt) * 2048;
            const uint32_t* __restrict__ Wlg = d_Wlo + (wlayer * 4 + kt) * 2048;
#pragma unroll
            for (int l = 0; l < 2; ++l) {
                int idx = tid + 256 * l;
                int n = idx >> 2;
                int q = idx & 3;
                uint4 h = *reinterpret_cast<const uint4*>(&Whg[n * 16 + 4 * q]);
                uint4 lo = *reinterpret_cast<const uint4*>(&Wlg[n * 16 + 4 * q]);
                *reinterpret_cast<uint4*>(&Whs[n][4 * q]) = h;
                *reinterpret_cast<uint4*>(&Wls[n][4 * q]) = lo;
            }
        }
        // X chunk load (+BN) + split
#pragma unroll
        for (int l = 0; l < 4; ++l) {
            int idx = tid + 256 * l;
            int r = idx >> 3;
            int c4 = idx & 7;
            int grow = row0 + r;
            float4 v = make_float4(0.f, 0.f, 0.f, 0.f);
            if (grow < M) {
                if (XH) {
                    int2 raw = __ldg(&Xh[grow * 32 + (k0 >> 2) + c4]);
                    float2 f0 = __half22float2(*reinterpret_cast<__half2*>(&raw.x));
                    float2 f1 = __half22float2(*reinterpret_cast<__half2*>(&raw.y));
                    v = make_float4(f0.x, f0.y, f1.x, f1.y);
                } else {
                    v = *reinterpret_cast<const float4*>(&Xf[grow * 128 + k0 + c4 * 4]);
                }
            }
            if (BN) {
                int k = k0 + c4 * 4;
                v.x = fmaxf(fmaf(v.x, ssc[k + 0], ssh[k + 0]), 0.f);
                v.y = fmaxf(fmaf(v.y, ssc[k + 1], ssh[k + 1]), 0.f);
                v.z = fmaxf(fmaf(v.z, ssc[k + 2], ssh[k + 2]), 0.f);
                v.w = fmaxf(fmaf(v.w, ssc[k + 3], ssh[k + 3]), 0.f);
            }
            __half hx, lx, hy, ly, hz, lz, hw, lw;
            h16_split(v.x, hx, lx);
            h16_split(v.y, hy, ly);
            h16_split(v.z, hz, lz);
            h16_split(v.w, hw, lw);
            Xhi[r][c4 * 2 + 0] = pack_h2(hx, hy);
            Xhi[r][c4 * 2 + 1] = pack_h2(hz, hw);
            Xlo[r][c4 * 2 + 0] = pack_h2(lx, ly);
            Xlo[r][c4 * 2 + 1] = pack_h2(lz, lw);
        }
        __syncthreads();

#pragma unroll
        for (int ks2 = 0; ks2 < 16; ks2 += 8) {
            uint32_t ahi[2][4], alo[2][4];
#pragma unroll
            for (int mt = 0; mt < 2; ++mt) {
                int rb = wm * 32 + mt * 16;
                ahi[mt][0] = Xhi[rb + gid][ks2 + tig];
                ahi[mt][1] = Xhi[rb + gid + 8][ks2 + tig];
                ahi[mt][2] = Xhi[rb + gid][ks2 + tig + 4];
                ahi[mt][3] = Xhi[rb + gid + 8][ks2 + tig + 4];
                alo[mt][0] = Xlo[rb + gid][ks2 + tig];
                alo[mt][1] = Xlo[rb + gid + 8][ks2 + tig];
                alo[mt][2] = Xlo[rb + gid][ks2 + tig + 4];
                alo[mt][3] = Xlo[rb + gid + 8][ks2 + tig + 4];
            }
#pragma unroll
            for (int nt = 0; nt < 8; ++nt) {
                int ncol = wn * 64 + nt * 8 + gid;
                uint32_t bh0 = Whs[ncol][ks2 + tig];
                uint32_t bh1 = Whs[ncol][ks2 + tig + 4];
                uint32_t bl0 = Wls[ncol][ks2 + tig];
                uint32_t bl1 = Wls[ncol][ks2 + tig + 4];
#pragma unroll
                for (int mt = 0; mt < 2; ++mt) {
                    mma_f16(c[mt][nt], ahi[mt], bh0, bh1);
                    mma_f16(c[mt][nt], alo[mt], bh0, bh1);
                    mma_f16(c[mt][nt], ahi[mt], bl0, bl1);
                }
            }
        }
        __syncthreads();
    }

    // fp16 epilogue: half index == feature index
#pragma unroll
    for (int mt = 0; mt < 2; ++mt) {
#pragma unroll
        for (int nt = 0; nt < 8; ++nt) {
            int col = wn * 64 + nt * 8 + 2 * tig;
            int r0 = row0 + wm * 32 + mt * 16 + gid;
            if (r0 < M)
                outh[r0 * 64 + (col >> 1)] =
                    __float22half2_rn(make_float2(c[mt][nt][0], c[mt][nt][1]));
            if (r0 + 8 < M)
                outh[(r0 + 8) * 64 + (col >> 1)] =
                    __float22half2_rn(make_float2(c[mt][nt][2], c[mt][nt][3]));
        }
    }
}

// phase A: gemm0 rows [0, gA) parallel with hist
__global__ __launch_bounds__(256) void fused0a_kernel(
    const float* __restrict__ x, __half2* __restrict__ outh,
    const int* __restrict__ er, int E, int M, int gA)
{
    if ((int)blockIdx.x < gA)
        gemm128_body<false, false>(x, outh, nullptr, nullptr, 0, 0, M, blockIdx.x);
    else
        hist_body(er, E, blockIdx.x - gA);
}

// phase B: gemm0 rows [gA, g128) parallel with scatter
__global__ __launch_bounds__(256) void fused0b_kernel(
    const float* __restrict__ x, __half2* __restrict__ outh,
    const int* __restrict__ er, const int* __restrict__ ec, const float* __restrict__ ew,
    int E, int M, int gA, int gemmB)
{
    if ((int)blockIdx.x < gemmB)
        gemm128_body<false, false>(x, outh, nullptr, nullptr, 0, 0, M, blockIdx.x + gA);
    else
        scatter_body(er, ec, ew, E, blockIdx.x - gemmB);
}

__global__ __launch_bounds__(256) void gemm128h_kernel(
    const int2* __restrict__ X, __half2* __restrict__ outh,
    const float* __restrict__ g, const float* __restrict__ be,
    int layer, int M)
{
    gemm128_body<true, true>(X, outh, g, be, 1, layer, M, blockIdx.x);
}

// ---------------- GEMM F=40 (fp16 in, fp32 compute, fp16 out, BN fused) ----------------
__global__ __launch_bounds__(256) void gemm40_kernel(
    const int2* __restrict__ Xh, const float* __restrict__ W,
    __half* __restrict__ outh,
    const float* __restrict__ g, const float* __restrict__ be,
    int layer, int M)
{
    constexpr int F = FOUT;
    __shared__ float Xs[64][64];
    __shared__ float Ws[64][F];
    __shared__ float ssc[128], ssh[128];

    const int tx = threadIdx.x;
    const int ty = threadIdx.y;
    const int tid = ty * 32 + tx;
    const int row0 = blockIdx.x * 64;

    if (tid < 128) {
        const float invN = 1.f / (float)NN;
        float mean = d_sum[layer][tid] * invN;
        float var = d_sumsq[layer][tid] * invN - mean * mean;
        float sc = g[tid] * rsqrtf(var + BN_EPS);
        ssc[tid] = sc;
        ssh[tid] = fmaf(-mean, sc, be[tid]);
    }
    __syncthreads();

    float acc[8][2];
#pragma unroll
    for (int i = 0; i < 8; ++i) { acc[i][0] = 0.f; acc[i][1] = 0.f; }

    for (int kt = 0; kt < 2; ++kt) {
        const int k0 = kt * 64;
        {
            const int nv4 = 64 * F / 4;
            for (int idx = tid; idx < nv4; idx += 256) {
                int r = idx / (F / 4);
                int c4 = idx % (F / 4);
                float4 v = *reinterpret_cast<const float4*>(&W[(k0 + r) * F + c4 * 4]);
                *reinterpret_cast<float4*>(&Ws[r][c4 * 4]) = v;
            }
        }
        {
#pragma unroll
            for (int l = 0; l < 4; ++l) {
                int idx = tid + 256 * l;
                int r = idx >> 4;
                int c4 = idx & 15;
                int grow = row0 + r;
                float4 v = make_float4(0.f, 0.f, 0.f, 0.f);
                if (grow < M) {
                    int2 raw = __ldg(&Xh[grow * 32 + (k0 >> 2) + c4]);
                    float2 f0 = __half22float2(*reinterpret_cast<__half2*>(&raw.x));
                    float2 f1 = __half22float2(*reinterpret_cast<__half2*>(&raw.y));
                    v = make_float4(f0.x, f0.y, f1.x, f1.y);
                }
                int k = k0 + c4 * 4;
                v.x = fmaxf(fmaf(v.x, ssc[k + 0], ssh[k + 0]), 0.f);
                v.y = fmaxf(fmaf(v.y, ssc[k + 1], ssh[k + 1]), 0.f);
                v.z = fmaxf(fmaf(v.z, ssc[k + 2], ssh[k + 2]), 0.f);
                v.w = fmaxf(fmaf(v.w, ssc[k + 3], ssh[k + 3]), 0.f);
                *reinterpret_cast<float4*>(&Xs[r][c4 * 4]) = v;
            }
        }
        __syncthreads();

#pragma unroll 4
        for (int kk = 0; kk < 64; ++kk) {
            float b0 = Ws[kk][tx];
            float b1 = (tx < 8) ? Ws[kk][32 + tx] : 0.f;
#pragma unroll
            for (int i = 0; i < 8; ++i) {
                float a = Xs[ty + 8 * i][kk];
                acc[i][0] = fmaf(a, b0, acc[i][0]);
                acc[i][1] = fmaf(a, b1, acc[i][1]);
            }
        }
        __syncthreads();
    }

#pragma unroll
    for (int i = 0; i < 8; ++i) {
        int grow = row0 + ty + 8 * i;
        if (grow < M) {
            outh[grow * F + tx] = __float2half_rn(acc[i][0]);
            if (tx < 8) outh[grow * F + 32 + tx] = __float2half_rn(acc[i][1]);
        }
    }
}

// ---------------- SpMM F=128 (fp16 gathers, fp16 out) + BN stats tree-reduce ----------------
__global__ __launch_bounds__(256) void spmm128_kernel(
    const int2* __restrict__ h,
    const float* __restrict__ bias,
    int2* __restrict__ outh, int layer, int M)
{
    __shared__ float sacc[8][128];
    const int warp = blockIdx.x * 8 + (threadIdx.x >> 5);
    const int wid = threadIdx.x >> 5;
    const int lane = threadIdx.x & 31;
    const int tid = threadIdx.x;

    float4 acc = make_float4(0.f, 0.f, 0.f, 0.f);
    if (warp < M) {
        const int s = d_rowptr[warp];
        const int e = d_rowptr[warp + 1];
        int base = s;
        for (; base + 32 <= e; base += 32) {
            int2 md = d_ecolw[base + lane];
            int colr = md.x;
            float wr = __int_as_float(md.y);
#pragma unroll
            for (int j = 0; j < 32; ++j) {
                int col = __shfl_sync(0xffffffffu, colr, j);
                float w = __shfl_sync(0xffffffffu, wr, j);
                int2 raw = __ldg(&h[col * 32 + lane]);
                float2 f0 = __half22float2(*reinterpret_cast<__half2*>(&raw.x));
                float2 f1 = __half22float2(*reinterpret_cast<__half2*>(&raw.y));
                acc.x = fmaf(w, f0.x, acc.x);
                acc.y = fmaf(w, f0.y, acc.y);
                acc.z = fmaf(w, f1.x, acc.z);
                acc.w = fmaf(w, f1.y, acc.w);
            }
        }
        if (base < e) {
            int n = e - base;
            int2 md = (lane < n) ? d_ecolw[base + lane] : make_int2(0, 0);
            int colr = md.x;
            float wr = __int_as_float(md.y);
            for (int j = 0; j < n; ++j) {
                int col = __shfl_sync(0xffffffffu, colr, j);
                float w = __shfl_sync(0xffffffffu, wr, j);
                int2 raw = __ldg(&h[col * 32 + lane]);
                float2 f0 = __half22float2(*reinterpret_cast<__half2*>(&raw.x));
                float2 f1 = __half22float2(*reinterpret_cast<__half2*>(&raw.y));
                acc.x = fmaf(w, f0.x, acc.x);
                acc.y = fmaf(w, f0.y, acc.y);
                acc.z = fmaf(w, f1.x, acc.z);
                acc.w = fmaf(w, f1.y, acc.w);
            }
        }
        const int f0i = lane * 4;
        float4 b = *reinterpret_cast<const float4*>(&bias[f0i]);
        acc.x += b.x; acc.y += b.y; acc.z += b.z; acc.w += b.w;
        __half2 h0 = __float22half2_rn(make_float2(acc.x, acc.y));
        __half2 h1 = __float22half2_rn(make_float2(acc.z, acc.w));
        int2 packed;
        packed.x = *reinterpret_cast<int*>(&h0);
        packed.y = *reinterpret_cast<int*>(&h1);
        outh[warp * 32 + lane] = packed;
    }
    *reinterpret_cast<float4*>(&sacc[wid][lane * 4]) = acc;
    __syncthreads();
    if (tid < 128) {
        float s = 0.f, s2 = 0.f;
#pragma unroll
        for (int w = 0; w < 8; ++w) {
            float v = sacc[w][tid];
            s += v;
            s2 = fmaf(v, v, s2);
        }
        atomicAdd(&d_sum[layer][tid], s);
        atomicAdd(&d_sumsq[layer][tid], s2);
    }
}

// ---------------- SpMM F=40 (fp16 gathers, fp32 accum & output) ----------------
__global__ __launch_bounds__(256) void spmm40_kernel(
    const __half2* __restrict__ h,
    const float* __restrict__ bias,
    float* __restrict__ out, int M)
{
    const int warp = blockIdx.x * 8 + (threadIdx.x >> 5);
    const int lane = threadIdx.x & 31;
    if (warp >= M) return;
    const int s = d_rowptr[warp];
    const int e = d_rowptr[warp + 1];

    float2 acc = make_float2(0.f, 0.f);
    int base = s;
    for (; base + 32 <= e; base += 32) {
        int2 md = d_ecolw[base + lane];
        int colr = md.x;
        float wr = __int_as_float(md.y);
#pragma unroll
        for (int j = 0; j < 32; ++j) {
            int col = __shfl_sync(0xffffffffu, colr, j);
            float w = __shfl_sync(0xffffffffu, wr, j);
            if (lane < 20) {
                float2 v = __half22float2(__ldg(&h[col * 20 + lane]));
                acc.x = fmaf(w, v.x, acc.x);
                acc.y = fmaf(w, v.y, acc.y);
            }
        }
    }
    if (base < e) {
        int n = e - base;
        int2 md = (lane < n) ? d_ecolw[base + lane] : make_int2(0, 0);
        int colr = md.x;
        float wr = __int_as_float(md.y);
        for (int j = 0; j < n; ++j) {
            int col = __shfl_sync(0xffffffffu, colr, j);
            float w = __shfl_sync(0xffffffffu, wr, j);
            if (lane < 20) {
                float2 v = __half22float2(__ldg(&h[col * 20 + lane]));
                acc.x = fmaf(w, v.x, acc.x);
                acc.y = fmaf(w, v.y, acc.y);
            }
        }
    }
    if (lane < 20) {
        acc.x += bias[2 * lane];
        acc.y += bias[2 * lane + 1];
        *reinterpret_cast<float2*>(&out[warp * FOUT + 2 * lane]) = acc;
    }
}

// ---------------- launch ----------------
extern "C" void kernel_launch(void* const* d_in, const int* in_sizes, int n_in,
                              void* d_out, int out_size)
{
    const float* x   = (const float*)d_in[0];
    const int*   er  = (const int*)d_in[1];
    const int*   ec  = (const int*)d_in[2];
    const float* ew  = (const float*)d_in[3];
    const float* W0  = (const float*)d_in[4];
    const float* b0  = (const float*)d_in[5];
    const float* g0  = (const float*)d_in[6];
    const float* be0 = (const float*)d_in[7];
    const float* W1  = (const float*)d_in[8];
    const float* b1  = (const float*)d_in[9];
    const float* g1  = (const float*)d_in[10];
    const float* be1 = (const float*)d_in[11];
    const float* W2  = (const float*)d_in[12];
    const float* b2  = (const float*)d_in[13];
    float* out = (float*)d_out;

    const int M = in_sizes[0] / FIN;
    const int E = in_sizes[1];

    int2*   t0h; cudaGetSymbolAddress((void**)&t0h, d_t0h);
    int2*   t1h; cudaGetSymbolAddress((void**)&t1h, d_t1h);
    __half* t2h; cudaGetSymbolAddress((void**)&t2h, d_t2h);

    const int g128 = (M + 127) / 128;
    const int gsp  = (M + 7) / 8;
    const int E4   = (E + 3) / 4;
    const int hB   = (E4 + 255) / 256;
    const int gA   = g128 / 2;            // gemm0 rows in phase A
    const int gemmB = g128 - gA;          // gemm0 rows in phase B

    // zero counts/sums + pre-split W0/W1
    zero_kernel<<<(NN + 255) / 256, 256>>>(W0, W1);
    // phase A: gemm0 first half ∥ hist
    fused0a_kernel<<<gA + hB, 256>>>(x, (__half2*)t0h, er, E, M, gA);
    scan_kernel<<<1, 1024>>>(M);
    // phase B: gemm0 second half ∥ scatter
    fused0b_kernel<<<gemmB + hB, 256>>>(x, (__half2*)t0h, er, ec, ew, E, M, gA, gemmB);

    // layer 0 aggregate
    spmm128_kernel<<<gsp, 256>>>(t0h, b0, t1h, 0, M);

    // layer 1 (BN finalize of layer-0 stats fused into gemm prologue)
    gemm128h_kernel<<<g128, 256>>>(t1h, (__half2*)t0h, g0, be0, 0, M);
    spmm128_kernel<<<gsp, 256>>>(t0h, b1, t1h, 1, M);

    // layer 2 (BN finalize of layer-1 stats fused into gemm40 prologue)
    gemm40_kernel<<<(M + 63) / 64, dim3(32, 8)>>>(t1h, W2, t2h, g1, be1, 1, M);
    spmm40_kernel<<<gsp, 256>>>((const __half2*)t2h, b2, out, M);
}